// round 6
// baseline (speedup 1.0000x reference)
#include <cuda_runtime.h>
#include <cuda_fp16.h>
#include <cstdint>

#define DD 128
#define NMAX 100000
#define EMAX 1600000
#define RESC 0.2f
#define LNEPS 1e-5f

// ---------------- scratch (static device globals; no allocs allowed) --------
__device__ __half g_t[NMAX * DD];      // GEMM input (LN'd features), fp16
__device__ __half g_xw[NMAX * DD];     // GEMM output (pre-aggregation), fp16
__device__ float  g_rout[NMAX];
__device__ float  g_rin[NMAX];
__device__ int    g_deg[2 * NMAX];     // [0,N)=degout, [N,2N)=degin
__device__ int    g_rowptr[NMAX + 1];
__device__ int    g_cursor[NMAX];
__device__ int    g_csrsrc[EMAX];
__device__ int    g_bsums[256];

// ---------------- degree (int) ----------------------------------------------
__global__ void degree_kernel(const int* __restrict__ src, const int* __restrict__ dst,
                              int* __restrict__ dout, int* __restrict__ din, int e) {
    int i = blockIdx.x * blockDim.x + threadIdx.x;
    if (i < e) {
        atomicAdd(dout + src[i], 1);
        atomicAdd(din + dst[i], 1);
    }
}

// ---------------- exclusive scan over degin ----------------------------------
__global__ void scan_block_kernel(const int* __restrict__ in, int* __restrict__ out,
                                  int* __restrict__ bsums, int n) {
    __shared__ int wsum[8];
    int t = threadIdx.x;
    int lane = t & 31, wid = t >> 5;
    int base = blockIdx.x * 1024 + t * 4;

    int v0 = (base + 0 < n) ? in[base + 0] : 0;
    int v1 = (base + 1 < n) ? in[base + 1] : 0;
    int v2 = (base + 2 < n) ? in[base + 2] : 0;
    int v3 = (base + 3 < n) ? in[base + 3] : 0;
    int tsum = v0 + v1 + v2 + v3;

    int x = tsum;
#pragma unroll
    for (int o = 1; o < 32; o <<= 1) {
        int y = __shfl_up_sync(0xFFFFFFFFu, x, o);
        if (lane >= o) x += y;
    }
    if (lane == 31) wsum[wid] = x;
    __syncthreads();
    if (wid == 0) {
        int w = (lane < 8) ? wsum[lane] : 0;
        int orig = w;
#pragma unroll
        for (int o = 1; o < 8; o <<= 1) {
            int y = __shfl_up_sync(0xFFFFFFFFu, w, o);
            if (lane >= o) w += y;
        }
        if (lane < 8) wsum[lane] = w - orig;
    }
    __syncthreads();

    int texcl = wsum[wid] + x - tsum;
    if (base + 0 < n) out[base + 0] = texcl;
    if (base + 1 < n) out[base + 1] = texcl + v0;
    if (base + 2 < n) out[base + 2] = texcl + v0 + v1;
    if (base + 3 < n) out[base + 3] = texcl + v0 + v1 + v2;
    if (t == 255) bsums[blockIdx.x] = wsum[7] + x;
}

__global__ void scan_spine_kernel(int* __restrict__ bsums, int nb) {
    __shared__ int sh[128];
    int t = threadIdx.x;
    int v = (t < nb) ? bsums[t] : 0;
    int orig = v;
#pragma unroll
    for (int o = 1; o < 128; o <<= 1) {
        sh[t] = v;
        __syncthreads();
        int y = (t >= o) ? sh[t - o] : 0;
        __syncthreads();
        v += y;
    }
    if (t < nb) bsums[t] = v - orig;
}

// fused: rowptr += spine; cursor = rowptr; rout/rin = rsqrt(max(deg,1))
__global__ void scan_add_kernel(int* __restrict__ out, int* __restrict__ cursor,
                                const int* __restrict__ bsums,
                                const int* __restrict__ degout, const int* __restrict__ degin,
                                float* __restrict__ rout, float* __restrict__ rin,
                                int n, int e) {
    int base = blockIdx.x * 1024 + threadIdx.x * 4;
    int add = bsums[blockIdx.x];
#pragma unroll
    for (int i = 0; i < 4; i++) {
        int idx = base + i;
        if (idx < n) {
            int v = out[idx] + add;
            out[idx] = v;
            cursor[idx] = v;
            rout[idx] = rsqrtf((float)max(degout[idx], 1));
            rin[idx]  = rsqrtf((float)max(degin[idx], 1));
        }
    }
    if (blockIdx.x == 0 && threadIdx.x == 0) out[n] = e;
}

__global__ void csr_fill_kernel(const int* __restrict__ src, const int* __restrict__ dst,
                                int* __restrict__ cursor, int* __restrict__ csr, int e) {
    int i = blockIdx.x * blockDim.x + threadIdx.x;
    if (i < e) {
        int p = atomicAdd(cursor + dst[i], 1);
        csr[p] = src[i];
    }
}

// ---------------- TF32 tensor-core GEMM, templated A type, fp16 output -------
// C[n,128] = A[n,128] @ W[128,128]   (no row scaling; applied in agg)
#define SST 136

__device__ __forceinline__ uint32_t f2tf32(float x) {
    uint32_t r;
    asm("cvt.rna.tf32.f32 %0, %1;" : "=r"(r) : "f"(x));
    return r;
}

__device__ __forceinline__ float4 ld4(const float* p) {
    return *(const float4*)p;
}
__device__ __forceinline__ float4 ld4(const __half* p) {
    uint2 u = *(const uint2*)p;
    float2 lo = __half22float2(*(const __half2*)&u.x);
    float2 hi = __half22float2(*(const __half2*)&u.y);
    return make_float4(lo.x, lo.y, hi.x, hi.y);
}

template <typename AT>
__global__ __launch_bounds__(256) void gemm_tf32_kernel(
    const AT* __restrict__ A, const float* __restrict__ W,
    __half* __restrict__ C, int n)
{
    __shared__ uint32_t sA[2][16 * SST];
    __shared__ uint32_t sW[2][16 * SST];

    int tid = threadIdx.x;
    int lane = tid & 31;
    int wrp = tid >> 5;
    int wm = wrp & 3;
    int wn = wrp >> 2;
    int tig = lane & 3;
    int gid = lane >> 2;
    int row0 = blockIdx.x * 128;

    int ar0 = tid >> 2;
    int ar1 = ar0 + 64;
    int ak0 = (tid & 3) << 2;
    int wk0 = tid >> 5;
    int wk1 = wk0 + 8;
    int wc4 = (tid & 31) << 2;

    bool rok0 = (row0 + ar0) < n;
    bool rok1 = (row0 + ar1) < n;
    const AT* Ap0 = A + (size_t)(row0 + ar0) * DD + ak0;
    const AT* Ap1 = A + (size_t)(row0 + ar1) * DD + ak0;
    const float* Wp0 = W + (size_t)wk0 * DD + wc4;
    const float* Wp1 = W + (size_t)wk1 * DD + wc4;

    float acc[2][8][4];
#pragma unroll
    for (int i = 0; i < 2; i++)
#pragma unroll
        for (int j = 0; j < 8; j++)
#pragma unroll
            for (int k = 0; k < 4; k++) acc[i][j][k] = 0.0f;

    float4 a0 = make_float4(0.f, 0.f, 0.f, 0.f), a1 = a0;
    if (rok0) a0 = ld4(Ap0);
    if (rok1) a1 = ld4(Ap1);
    float4 w0 = ld4(Wp0);
    float4 w1 = ld4(Wp1);

    {
        uint32_t* pA = &sA[0][0];
        pA[(ak0 + 0) * SST + ar0] = f2tf32(a0.x);
        pA[(ak0 + 1) * SST + ar0] = f2tf32(a0.y);
        pA[(ak0 + 2) * SST + ar0] = f2tf32(a0.z);
        pA[(ak0 + 3) * SST + ar0] = f2tf32(a0.w);
        pA[(ak0 + 0) * SST + ar1] = f2tf32(a1.x);
        pA[(ak0 + 1) * SST + ar1] = f2tf32(a1.y);
        pA[(ak0 + 2) * SST + ar1] = f2tf32(a1.z);
        pA[(ak0 + 3) * SST + ar1] = f2tf32(a1.w);
        uint32_t* pW = &sW[0][0];
        uint4 u0 = make_uint4(f2tf32(w0.x), f2tf32(w0.y), f2tf32(w0.z), f2tf32(w0.w));
        uint4 u1 = make_uint4(f2tf32(w1.x), f2tf32(w1.y), f2tf32(w1.z), f2tf32(w1.w));
        *(uint4*)&pW[wk0 * SST + wc4] = u0;
        *(uint4*)&pW[wk1 * SST + wc4] = u1;
    }
    __syncthreads();

#pragma unroll
    for (int s = 0; s < 8; s++) {
        int cur = s & 1;
        if (s < 7) {
            int kb = (s + 1) * 16;
            a0 = make_float4(0.f, 0.f, 0.f, 0.f); a1 = a0;
            if (rok0) a0 = ld4(Ap0 + kb);
            if (rok1) a1 = ld4(Ap1 + kb);
            w0 = ld4(Wp0 + (size_t)kb * DD);
            w1 = ld4(Wp1 + (size_t)kb * DD);
        }

        const uint32_t* pA = &sA[cur][0];
        const uint32_t* pW = &sW[cur][0];
#pragma unroll
        for (int ks = 0; ks < 2; ks++) {
            int k0 = ks * 8;
            uint32_t af[2][4];
#pragma unroll
            for (int mt = 0; mt < 2; mt++) {
                int rb = wm * 32 + mt * 16 + gid;
                af[mt][0] = pA[(k0 + tig) * SST + rb];
                af[mt][1] = pA[(k0 + tig) * SST + rb + 8];
                af[mt][2] = pA[(k0 + tig + 4) * SST + rb];
                af[mt][3] = pA[(k0 + tig + 4) * SST + rb + 8];
            }
#pragma unroll
            for (int nt = 0; nt < 8; nt++) {
                int cb = wn * 64 + nt * 8 + gid;
                uint32_t b0 = pW[(k0 + tig) * SST + cb];
                uint32_t b1 = pW[(k0 + tig + 4) * SST + cb];
#pragma unroll
                for (int mt = 0; mt < 2; mt++) {
                    asm volatile(
                        "mma.sync.aligned.m16n8k8.row.col.f32.tf32.tf32.f32 "
                        "{%0,%1,%2,%3}, {%4,%5,%6,%7}, {%8,%9}, {%0,%1,%2,%3};"
                        : "+f"(acc[mt][nt][0]), "+f"(acc[mt][nt][1]),
                          "+f"(acc[mt][nt][2]), "+f"(acc[mt][nt][3])
                        : "r"(af[mt][0]), "r"(af[mt][1]), "r"(af[mt][2]), "r"(af[mt][3]),
                          "r"(b0), "r"(b1));
                }
            }
        }

        if (s < 7) {
            int nb = cur ^ 1;
            uint32_t* qA = &sA[nb][0];
            qA[(ak0 + 0) * SST + ar0] = f2tf32(a0.x);
            qA[(ak0 + 1) * SST + ar0] = f2tf32(a0.y);
            qA[(ak0 + 2) * SST + ar0] = f2tf32(a0.z);
            qA[(ak0 + 3) * SST + ar0] = f2tf32(a0.w);
            qA[(ak0 + 0) * SST + ar1] = f2tf32(a1.x);
            qA[(ak0 + 1) * SST + ar1] = f2tf32(a1.y);
            qA[(ak0 + 2) * SST + ar1] = f2tf32(a1.z);
            qA[(ak0 + 3) * SST + ar1] = f2tf32(a1.w);
            uint32_t* qW = &sW[nb][0];
            uint4 u0 = make_uint4(f2tf32(w0.x), f2tf32(w0.y), f2tf32(w0.z), f2tf32(w0.w));
            uint4 u1 = make_uint4(f2tf32(w1.x), f2tf32(w1.y), f2tf32(w1.z), f2tf32(w1.w));
            *(uint4*)&qW[wk0 * SST + wc4] = u0;
            *(uint4*)&qW[wk1 * SST + wc4] = u1;
            __syncthreads();
        }
    }

#pragma unroll
    for (int mt = 0; mt < 2; mt++) {
        int r0 = row0 + wm * 32 + mt * 16 + gid;
        int r1 = r0 + 8;
#pragma unroll
        for (int nt = 0; nt < 8; nt++) {
            int col = wn * 64 + nt * 8 + tig * 2;
            if (r0 < n)
                *(__half2*)(C + (size_t)r0 * DD + col) =
                    __floats2half2_rn(acc[mt][nt][0], acc[mt][nt][1]);
            if (r1 < n)
                *(__half2*)(C + (size_t)r1 * DD + col) =
                    __floats2half2_rn(acc[mt][nt][2], acc[mt][nt][3]);
        }
    }
}

// ---------------- fused CSR aggregate (fp16 + rout[src] scale) + epilogue ---
__device__ __forceinline__ void acc_u2(uint2 u, float r,
                                       float& ax, float& ay, float& az, float& aw) {
    float2 lo = __half22float2(*(const __half2*)&u.x);
    float2 hi = __half22float2(*(const __half2*)&u.y);
    ax = fmaf(lo.x, r, ax); ay = fmaf(lo.y, r, ay);
    az = fmaf(hi.x, r, az); aw = fmaf(hi.y, r, aw);
}

template <bool DO_LN, typename OT>
__global__ void agg_kernel(const int* __restrict__ rowptr, const int* __restrict__ csr,
                           const __half* __restrict__ xw, const float* __restrict__ rout,
                           const float* __restrict__ rin,
                           const float* __restrict__ bias, const float* __restrict__ feat,
                           const float* __restrict__ lng, const float* __restrict__ lnb,
                           OT* __restrict__ o, int n)
{
    int row = blockIdx.x * 8 + (threadIdx.x >> 5);
    if (row >= n) return;
    int lane = threadIdx.x & 31;

    int beg = __ldg(rowptr + row);
    int end = __ldg(rowptr + row + 1);

    const uint2* xwv = (const uint2*)xw + lane;
    float ax = 0.f, ay = 0.f, az = 0.f, aw = 0.f;

    int e = beg;
    for (; e + 8 <= end; e += 8) {
        int s[8];
#pragma unroll
        for (int q = 0; q < 8; q++) s[q] = __ldg(csr + e + q);
        uint2 u[8];
        float ro[8];
#pragma unroll
        for (int q = 0; q < 8; q++) {
            u[q] = __ldg(xwv + (size_t)s[q] * 32);
            ro[q] = __ldg(rout + s[q]);
        }
#pragma unroll
        for (int q = 0; q < 8; q++) acc_u2(u[q], ro[q], ax, ay, az, aw);
    }
    if (e + 4 <= end) {
        int s[4];
#pragma unroll
        for (int q = 0; q < 4; q++) s[q] = __ldg(csr + e + q);
        uint2 u[4];
        float ro[4];
#pragma unroll
        for (int q = 0; q < 4; q++) {
            u[q] = __ldg(xwv + (size_t)s[q] * 32);
            ro[q] = __ldg(rout + s[q]);
        }
#pragma unroll
        for (int q = 0; q < 4; q++) acc_u2(u[q], ro[q], ax, ay, az, aw);
        e += 4;
    }
    if (e + 2 <= end) {
        int s0 = __ldg(csr + e), s1 = __ldg(csr + e + 1);
        uint2 u0 = __ldg(xwv + (size_t)s0 * 32);
        uint2 u1 = __ldg(xwv + (size_t)s1 * 32);
        float r0 = __ldg(rout + s0), r1 = __ldg(rout + s1);
        acc_u2(u0, r0, ax, ay, az, aw);
        acc_u2(u1, r1, ax, ay, az, aw);
        e += 2;
    }
    if (e < end) {
        int s0 = __ldg(csr + e);
        acc_u2(__ldg(xwv + (size_t)s0 * 32), __ldg(rout + s0), ax, ay, az, aw);
    }

    float s = __ldg(rin + row);
    float4 bb = ((const float4*)bias)[lane];
    float4 f = __ldg((const float4*)feat + (size_t)row * 32 + lane);
    float4 h;
    h.x = fmaf(ax, s, bb.x) + RESC * f.x;
    h.y = fmaf(ay, s, bb.y) + RESC * f.y;
    h.z = fmaf(az, s, bb.z) + RESC * f.z;
    h.w = fmaf(aw, s, bb.w) + RESC * f.w;

    if (!DO_LN) {
        ((float4*)((float*)o + (size_t)row * DD))[lane] = h;
        return;
    }

    float sum = h.x + h.y + h.z + h.w;
#pragma unroll
    for (int off = 16; off > 0; off >>= 1) sum += __shfl_xor_sync(0xFFFFFFFFu, sum, off);
    float mu = sum * (1.0f / 128.0f);

    float dx = h.x - mu, dy = h.y - mu, dz = h.z - mu, dw = h.w - mu;
    float sq = dx * dx + dy * dy + dz * dz + dw * dw;
#pragma unroll
    for (int off = 16; off > 0; off >>= 1) sq += __shfl_xor_sync(0xFFFFFFFFu, sq, off);
    float inv = rsqrtf(sq * (1.0f / 128.0f) + LNEPS);

    float4 gg = ((const float4*)lng)[lane];
    float4 lb = ((const float4*)lnb)[lane];
    float rx = fmaxf(fmaf(dx * inv, gg.x, lb.x), 0.0f);
    float ry = fmaxf(fmaf(dy * inv, gg.y, lb.y), 0.0f);
    float rz = fmaxf(fmaf(dz * inv, gg.z, lb.z), 0.0f);
    float rw = fmaxf(fmaf(dw * inv, gg.w, lb.w), 0.0f);
    uint2 w;
    *(__half2*)&w.x = __floats2half2_rn(rx, ry);
    *(__half2*)&w.y = __floats2half2_rn(rz, rw);
    ((uint2*)((__half*)o + (size_t)row * DD))[lane] = w;
}

// ---------------- launch ------------------------------------------------------
extern "C" void kernel_launch(void* const* d_in, const int* in_sizes, int n_in,
                              void* d_out, int out_size)
{
    const int*   src     = (const int*)d_in[0];
    const int*   dst     = (const int*)d_in[1];
    const float* in_feat = (const float*)d_in[2];
    const float* W1      = (const float*)d_in[3];
    const float* b1      = (const float*)d_in[4];
    const float* W2      = (const float*)d_in[5];
    const float* b2      = (const float*)d_in[6];
    const float* ln1g    = (const float*)d_in[7];
    const float* ln1b    = (const float*)d_in[8];
    const float* ln2g    = (const float*)d_in[9];
    const float* ln2b    = (const float*)d_in[10];
    float* out = (float*)d_out;

    int E = in_sizes[0];
    int n = in_sizes[2] / DD;

    __half *t, *xw;
    float *rout, *rin;
    int *deg, *rowptr, *cursor, *csrsrc, *bsums;
    cudaGetSymbolAddress((void**)&t,      g_t);
    cudaGetSymbolAddress((void**)&xw,     g_xw);
    cudaGetSymbolAddress((void**)&rout,   g_rout);
    cudaGetSymbolAddress((void**)&rin,    g_rin);
    cudaGetSymbolAddress((void**)&deg,    g_deg);
    cudaGetSymbolAddress((void**)&rowptr, g_rowptr);
    cudaGetSymbolAddress((void**)&cursor, g_cursor);
    cudaGetSymbolAddress((void**)&csrsrc, g_csrsrc);
    cudaGetSymbolAddress((void**)&bsums,  g_bsums);
    int* degout = deg;
    int* degin  = deg + NMAX;

    const int TB = 256;
    int gridE    = (E + TB - 1) / TB;
    int gridRow  = (n + 7) / 8;
    int gridGemm = (n + 127) / 128;
    int gridScan = (n + 1023) / 1024;

    // launches 1-5 (skipped by ncu -s 5): memset, degree, scan_block, scan_spine, scan_add
    cudaMemsetAsync(deg, 0, 2 * NMAX * sizeof(int));
    degree_kernel<<<gridE, TB>>>(src, dst, degout, degin, E);
    scan_block_kernel<<<gridScan, 256>>>(degin, rowptr, bsums, n);
    scan_spine_kernel<<<1, 128>>>(bsums, gridScan);
    scan_add_kernel<<<gridScan, 256>>>(rowptr, cursor, bsums, degout, degin, rout, rin, n, E);

    // launch 6 (ncu capture target): conv1 GEMM (independent of graph preproc now)
    gemm_tf32_kernel<float><<<gridGemm, TB>>>(in_feat, W1, xw, n);

    csr_fill_kernel<<<gridE, TB>>>(src, dst, cursor, csrsrc, E);

    // ---- conv1 agg (+LN1) -> t
    agg_kernel<true, __half><<<gridRow, TB>>>(rowptr, csrsrc, xw, rout, rin, b1, in_feat,
                                              ln1g, ln1b, t, n);

    // ---- conv2
    gemm_tf32_kernel<__half><<<gridGemm, TB>>>(t, W2, xw, n);
    agg_kernel<true, __half><<<gridRow, TB>>>(rowptr, csrsrc, xw, rout, rin, b2, in_feat,
                                              ln2g, ln2b, t, n);

    // ---- conv3
    gemm_tf32_kernel<__half><<<gridGemm, TB>>>(t, W2, xw, n);
    agg_kernel<false, float><<<gridRow, TB>>>(rowptr, csrsrc, xw, rout, rin, b2, in_feat,
                                              nullptr, nullptr, out, n);
}

// round 7
// speedup vs baseline: 1.0632x; 1.0632x over previous
#include <cuda_runtime.h>
#include <cuda_fp16.h>
#include <cstdint>

#define DD 128
#define NMAX 100000
#define EMAX 1600000
#define RESC 0.2f
#define LNEPS 1e-5f

// ---------------- scratch (static device globals; no allocs allowed) --------
__device__ __half g_t[NMAX * DD];      // GEMM input (LN'd features), fp16
__device__ __half g_xw[NMAX * DD];     // GEMM output (pre-aggregation), fp16
__device__ float  g_rout[NMAX];
__device__ float  g_rin[NMAX];
__device__ int    g_deg[2 * NMAX];     // [0,N)=degout, [N,2N)=degin
__device__ int    g_rowptr[NMAX + 1];
__device__ int    g_cursor[NMAX];
__device__ int    g_csrsrc[EMAX];
__device__ int    g_bsums[256];

// ---------------- degree (int) ----------------------------------------------
__global__ void degree_kernel(const int* __restrict__ src, const int* __restrict__ dst,
                              int* __restrict__ dout, int* __restrict__ din, int e) {
    int i = blockIdx.x * blockDim.x + threadIdx.x;
    if (i < e) {
        atomicAdd(dout + src[i], 1);
        atomicAdd(din + dst[i], 1);
    }
}

// ---------------- exclusive scan over degin ----------------------------------
__global__ void scan_block_kernel(const int* __restrict__ in, int* __restrict__ out,
                                  int* __restrict__ bsums, int n) {
    __shared__ int wsum[8];
    int t = threadIdx.x;
    int lane = t & 31, wid = t >> 5;
    int base = blockIdx.x * 1024 + t * 4;

    int v0 = (base + 0 < n) ? in[base + 0] : 0;
    int v1 = (base + 1 < n) ? in[base + 1] : 0;
    int v2 = (base + 2 < n) ? in[base + 2] : 0;
    int v3 = (base + 3 < n) ? in[base + 3] : 0;
    int tsum = v0 + v1 + v2 + v3;

    int x = tsum;
#pragma unroll
    for (int o = 1; o < 32; o <<= 1) {
        int y = __shfl_up_sync(0xFFFFFFFFu, x, o);
        if (lane >= o) x += y;
    }
    if (lane == 31) wsum[wid] = x;
    __syncthreads();
    if (wid == 0) {
        int w = (lane < 8) ? wsum[lane] : 0;
        int orig = w;
#pragma unroll
        for (int o = 1; o < 8; o <<= 1) {
            int y = __shfl_up_sync(0xFFFFFFFFu, w, o);
            if (lane >= o) w += y;
        }
        if (lane < 8) wsum[lane] = w - orig;
    }
    __syncthreads();

    int texcl = wsum[wid] + x - tsum;
    if (base + 0 < n) out[base + 0] = texcl;
    if (base + 1 < n) out[base + 1] = texcl + v0;
    if (base + 2 < n) out[base + 2] = texcl + v0 + v1;
    if (base + 3 < n) out[base + 3] = texcl + v0 + v1 + v2;
    if (t == 255) bsums[blockIdx.x] = wsum[7] + x;
}

__global__ void scan_spine_kernel(int* __restrict__ bsums, int nb) {
    __shared__ int sh[128];
    int t = threadIdx.x;
    int v = (t < nb) ? bsums[t] : 0;
    int orig = v;
#pragma unroll
    for (int o = 1; o < 128; o <<= 1) {
        sh[t] = v;
        __syncthreads();
        int y = (t >= o) ? sh[t - o] : 0;
        __syncthreads();
        v += y;
    }
    if (t < nb) bsums[t] = v - orig;
}

// fused: rowptr += spine; cursor = rowptr; rout/rin = rsqrt(max(deg,1))
__global__ void scan_add_kernel(int* __restrict__ out, int* __restrict__ cursor,
                                const int* __restrict__ bsums,
                                const int* __restrict__ degout, const int* __restrict__ degin,
                                float* __restrict__ rout, float* __restrict__ rin,
                                int n, int e) {
    int base = blockIdx.x * 1024 + threadIdx.x * 4;
    int add = bsums[blockIdx.x];
#pragma unroll
    for (int i = 0; i < 4; i++) {
        int idx = base + i;
        if (idx < n) {
            int v = out[idx] + add;
            out[idx] = v;
            cursor[idx] = v;
            rout[idx] = rsqrtf((float)max(degout[idx], 1));
            rin[idx]  = rsqrtf((float)max(degin[idx], 1));
        }
    }
    if (blockIdx.x == 0 && threadIdx.x == 0) out[n] = e;
}

__global__ void csr_fill_kernel(const int* __restrict__ src, const int* __restrict__ dst,
                                int* __restrict__ cursor, int* __restrict__ csr, int e) {
    int i = blockIdx.x * blockDim.x + threadIdx.x;
    if (i < e) {
        int p = atomicAdd(cursor + dst[i], 1);
        csr[p] = src[i];
    }
}

// ---------------- TF32 tensor-core GEMM, templated A type, fp16 output -------
// C[n,128] = (rs ? diag(rs) : I) A[n,128] @ W[128,128]
#define SST 136

__device__ __forceinline__ uint32_t f2tf32(float x) {
    uint32_t r;
    asm("cvt.rna.tf32.f32 %0, %1;" : "=r"(r) : "f"(x));
    return r;
}

__device__ __forceinline__ float4 ld4(const float* p) {
    return *(const float4*)p;
}
__device__ __forceinline__ float4 ld4(const __half* p) {
    uint2 u = *(const uint2*)p;
    float2 lo = __half22float2(*(const __half2*)&u.x);
    float2 hi = __half22float2(*(const __half2*)&u.y);
    return make_float4(lo.x, lo.y, hi.x, hi.y);
}

template <typename AT>
__global__ __launch_bounds__(256) void gemm_tf32_kernel(
    const AT* __restrict__ A, const float* __restrict__ W,
    const float* __restrict__ rs, __half* __restrict__ C, int n)
{
    __shared__ uint32_t sA[2][16 * SST];
    __shared__ uint32_t sW[2][16 * SST];

    int tid = threadIdx.x;
    int lane = tid & 31;
    int wrp = tid >> 5;
    int wm = wrp & 3;
    int wn = wrp >> 2;
    int tig = lane & 3;
    int gid = lane >> 2;
    int row0 = blockIdx.x * 128;

    int ar0 = tid >> 2;
    int ar1 = ar0 + 64;
    int ak0 = (tid & 3) << 2;
    int wk0 = tid >> 5;
    int wk1 = wk0 + 8;
    int wc4 = (tid & 31) << 2;

    bool rok0 = (row0 + ar0) < n;
    bool rok1 = (row0 + ar1) < n;
    float sc0 = 1.0f, sc1 = 1.0f;
    if (rs != nullptr) {
        if (rok0) sc0 = __ldg(rs + row0 + ar0);
        if (rok1) sc1 = __ldg(rs + row0 + ar1);
    }
    const AT* Ap0 = A + (size_t)(row0 + ar0) * DD + ak0;
    const AT* Ap1 = A + (size_t)(row0 + ar1) * DD + ak0;
    const float* Wp0 = W + (size_t)wk0 * DD + wc4;
    const float* Wp1 = W + (size_t)wk1 * DD + wc4;

    float acc[2][8][4];
#pragma unroll
    for (int i = 0; i < 2; i++)
#pragma unroll
        for (int j = 0; j < 8; j++)
#pragma unroll
            for (int k = 0; k < 4; k++) acc[i][j][k] = 0.0f;

    float4 a0 = make_float4(0.f, 0.f, 0.f, 0.f), a1 = a0;
    if (rok0) a0 = ld4(Ap0);
    if (rok1) a1 = ld4(Ap1);
    float4 w0 = ld4(Wp0);
    float4 w1 = ld4(Wp1);

    {
        uint32_t* pA = &sA[0][0];
        pA[(ak0 + 0) * SST + ar0] = f2tf32(a0.x * sc0);
        pA[(ak0 + 1) * SST + ar0] = f2tf32(a0.y * sc0);
        pA[(ak0 + 2) * SST + ar0] = f2tf32(a0.z * sc0);
        pA[(ak0 + 3) * SST + ar0] = f2tf32(a0.w * sc0);
        pA[(ak0 + 0) * SST + ar1] = f2tf32(a1.x * sc1);
        pA[(ak0 + 1) * SST + ar1] = f2tf32(a1.y * sc1);
        pA[(ak0 + 2) * SST + ar1] = f2tf32(a1.z * sc1);
        pA[(ak0 + 3) * SST + ar1] = f2tf32(a1.w * sc1);
        uint32_t* pW = &sW[0][0];
        uint4 u0 = make_uint4(f2tf32(w0.x), f2tf32(w0.y), f2tf32(w0.z), f2tf32(w0.w));
        uint4 u1 = make_uint4(f2tf32(w1.x), f2tf32(w1.y), f2tf32(w1.z), f2tf32(w1.w));
        *(uint4*)&pW[wk0 * SST + wc4] = u0;
        *(uint4*)&pW[wk1 * SST + wc4] = u1;
    }
    __syncthreads();

#pragma unroll
    for (int s = 0; s < 8; s++) {
        int cur = s & 1;
        if (s < 7) {
            int kb = (s + 1) * 16;
            a0 = make_float4(0.f, 0.f, 0.f, 0.f); a1 = a0;
            if (rok0) a0 = ld4(Ap0 + kb);
            if (rok1) a1 = ld4(Ap1 + kb);
            w0 = ld4(Wp0 + (size_t)kb * DD);
            w1 = ld4(Wp1 + (size_t)kb * DD);
        }

        const uint32_t* pA = &sA[cur][0];
        const uint32_t* pW = &sW[cur][0];
#pragma unroll
        for (int ks = 0; ks < 2; ks++) {
            int k0 = ks * 8;
            uint32_t af[2][4];
#pragma unroll
            for (int mt = 0; mt < 2; mt++) {
                int rb = wm * 32 + mt * 16 + gid;
                af[mt][0] = pA[(k0 + tig) * SST + rb];
                af[mt][1] = pA[(k0 + tig) * SST + rb + 8];
                af[mt][2] = pA[(k0 + tig + 4) * SST + rb];
                af[mt][3] = pA[(k0 + tig + 4) * SST + rb + 8];
            }
#pragma unroll
            for (int nt = 0; nt < 8; nt++) {
                int cb = wn * 64 + nt * 8 + gid;
                uint32_t b0 = pW[(k0 + tig) * SST + cb];
                uint32_t b1 = pW[(k0 + tig + 4) * SST + cb];
#pragma unroll
                for (int mt = 0; mt < 2; mt++) {
                    asm volatile(
                        "mma.sync.aligned.m16n8k8.row.col.f32.tf32.tf32.f32 "
                        "{%0,%1,%2,%3}, {%4,%5,%6,%7}, {%8,%9}, {%0,%1,%2,%3};"
                        : "+f"(acc[mt][nt][0]), "+f"(acc[mt][nt][1]),
                          "+f"(acc[mt][nt][2]), "+f"(acc[mt][nt][3])
                        : "r"(af[mt][0]), "r"(af[mt][1]), "r"(af[mt][2]), "r"(af[mt][3]),
                          "r"(b0), "r"(b1));
                }
            }
        }

        if (s < 7) {
            int nb = cur ^ 1;
            uint32_t* qA = &sA[nb][0];
            qA[(ak0 + 0) * SST + ar0] = f2tf32(a0.x * sc0);
            qA[(ak0 + 1) * SST + ar0] = f2tf32(a0.y * sc0);
            qA[(ak0 + 2) * SST + ar0] = f2tf32(a0.z * sc0);
            qA[(ak0 + 3) * SST + ar0] = f2tf32(a0.w * sc0);
            qA[(ak0 + 0) * SST + ar1] = f2tf32(a1.x * sc1);
            qA[(ak0 + 1) * SST + ar1] = f2tf32(a1.y * sc1);
            qA[(ak0 + 2) * SST + ar1] = f2tf32(a1.z * sc1);
            qA[(ak0 + 3) * SST + ar1] = f2tf32(a1.w * sc1);
            uint32_t* qW = &sW[nb][0];
            uint4 u0 = make_uint4(f2tf32(w0.x), f2tf32(w0.y), f2tf32(w0.z), f2tf32(w0.w));
            uint4 u1 = make_uint4(f2tf32(w1.x), f2tf32(w1.y), f2tf32(w1.z), f2tf32(w1.w));
            *(uint4*)&qW[wk0 * SST + wc4] = u0;
            *(uint4*)&qW[wk1 * SST + wc4] = u1;
            __syncthreads();
        }
    }

#pragma unroll
    for (int mt = 0; mt < 2; mt++) {
        int r0 = row0 + wm * 32 + mt * 16 + gid;
        int r1 = r0 + 8;
#pragma unroll
        for (int nt = 0; nt < 8; nt++) {
            int col = wn * 64 + nt * 8 + tig * 2;
            if (r0 < n)
                *(__half2*)(C + (size_t)r0 * DD + col) =
                    __floats2half2_rn(acc[mt][nt][0], acc[mt][nt][1]);
            if (r1 < n)
                *(__half2*)(C + (size_t)r1 * DD + col) =
                    __floats2half2_rn(acc[mt][nt][2], acc[mt][nt][3]);
        }
    }
}

// ---------------- fused CSR aggregate: half-warp per row, uint4 loads --------
// 16 lanes x 16B = 256B row (128 fp16). 256 threads -> 16 rows per block.
__device__ __forceinline__ void acc_u4(uint4 u, float* a) {
    float2 p0 = __half22float2(*(const __half2*)&u.x);
    float2 p1 = __half22float2(*(const __half2*)&u.y);
    float2 p2 = __half22float2(*(const __half2*)&u.z);
    float2 p3 = __half22float2(*(const __half2*)&u.w);
    a[0] += p0.x; a[1] += p0.y; a[2] += p1.x; a[3] += p1.y;
    a[4] += p2.x; a[5] += p2.y; a[6] += p3.x; a[7] += p3.y;
}

template <bool DO_LN, typename OT>
__global__ void agg_kernel(const int* __restrict__ rowptr, const int* __restrict__ csr,
                           const __half* __restrict__ xw, const float* __restrict__ rin,
                           const float* __restrict__ bias, const float* __restrict__ feat,
                           const float* __restrict__ lng, const float* __restrict__ lnb,
                           const float* __restrict__ rout, OT* __restrict__ o, int n)
{
    int row = blockIdx.x * 16 + (threadIdx.x >> 4);
    if (row >= n) return;
    int l16 = threadIdx.x & 15;

    int beg = __ldg(rowptr + row);
    int end = __ldg(rowptr + row + 1);

    const uint4* xwv = (const uint4*)xw + l16;  // row stride = 16 uint4
    float a[8] = {0.f, 0.f, 0.f, 0.f, 0.f, 0.f, 0.f, 0.f};

    int e = beg;
    for (; e + 8 <= end; e += 8) {
        int s[8];
#pragma unroll
        for (int q = 0; q < 8; q++) s[q] = __ldg(csr + e + q);
        uint4 u[8];
#pragma unroll
        for (int q = 0; q < 8; q++) u[q] = __ldg(xwv + (size_t)s[q] * 16);
#pragma unroll
        for (int q = 0; q < 8; q++) acc_u4(u[q], a);
    }
    if (e + 4 <= end) {
        int s[4];
#pragma unroll
        for (int q = 0; q < 4; q++) s[q] = __ldg(csr + e + q);
        uint4 u[4];
#pragma unroll
        for (int q = 0; q < 4; q++) u[q] = __ldg(xwv + (size_t)s[q] * 16);
#pragma unroll
        for (int q = 0; q < 4; q++) acc_u4(u[q], a);
        e += 4;
    }
    if (e + 2 <= end) {
        int s0 = __ldg(csr + e), s1 = __ldg(csr + e + 1);
        uint4 u0 = __ldg(xwv + (size_t)s0 * 16);
        uint4 u1 = __ldg(xwv + (size_t)s1 * 16);
        acc_u4(u0, a);
        acc_u4(u1, a);
        e += 2;
    }
    if (e < end) {
        int s0 = __ldg(csr + e);
        acc_u4(__ldg(xwv + (size_t)s0 * 16), a);
    }

    // epilogue: h = a * rin[row] + bias + 0.2*feat   (8 cols per lane)
    float s = __ldg(rin + row);
    float4 b0 = ((const float4*)bias)[l16 * 2];
    float4 b1 = ((const float4*)bias)[l16 * 2 + 1];
    float4 f0 = __ldg((const float4*)feat + (size_t)row * 32 + l16 * 2);
    float4 f1 = __ldg((const float4*)feat + (size_t)row * 32 + l16 * 2 + 1);
    float h[8];
    h[0] = fmaf(a[0], s, b0.x) + RESC * f0.x;
    h[1] = fmaf(a[1], s, b0.y) + RESC * f0.y;
    h[2] = fmaf(a[2], s, b0.z) + RESC * f0.z;
    h[3] = fmaf(a[3], s, b0.w) + RESC * f0.w;
    h[4] = fmaf(a[4], s, b1.x) + RESC * f1.x;
    h[5] = fmaf(a[5], s, b1.y) + RESC * f1.y;
    h[6] = fmaf(a[6], s, b1.z) + RESC * f1.z;
    h[7] = fmaf(a[7], s, b1.w) + RESC * f1.w;

    if (!DO_LN) {
        float* op = (float*)o + (size_t)row * DD + l16 * 8;
        *(float4*)op = make_float4(h[0], h[1], h[2], h[3]);
        *(float4*)(op + 4) = make_float4(h[4], h[5], h[6], h[7]);
        return;
    }

    // LN over 16 lanes (xor offsets stay within the half-warp group)
    float sum = 0.f;
#pragma unroll
    for (int q = 0; q < 8; q++) sum += h[q];
#pragma unroll
    for (int off = 8; off > 0; off >>= 1) sum += __shfl_xor_sync(0xFFFFFFFFu, sum, off);
    float mu = sum * (1.0f / 128.0f);

    float d[8], sq = 0.f;
#pragma unroll
    for (int q = 0; q < 8; q++) { d[q] = h[q] - mu; sq += d[q] * d[q]; }
#pragma unroll
    for (int off = 8; off > 0; off >>= 1) sq += __shfl_xor_sync(0xFFFFFFFFu, sq, off);
    float inv = rsqrtf(sq * (1.0f / 128.0f) + LNEPS);

    float ro = __ldg(rout + row);
    float4 g0 = ((const float4*)lng)[l16 * 2];
    float4 g1 = ((const float4*)lng)[l16 * 2 + 1];
    float4 lb0 = ((const float4*)lnb)[l16 * 2];
    float4 lb1 = ((const float4*)lnb)[l16 * 2 + 1];
    float gg[8] = {g0.x, g0.y, g0.z, g0.w, g1.x, g1.y, g1.z, g1.w};
    float lb[8] = {lb0.x, lb0.y, lb0.z, lb0.w, lb1.x, lb1.y, lb1.z, lb1.w};

    float r[8];
#pragma unroll
    for (int q = 0; q < 8; q++)
        r[q] = fmaxf(fmaf(d[q] * inv, gg[q], lb[q]), 0.0f) * ro;

    uint4 w;
    *(__half2*)&w.x = __floats2half2_rn(r[0], r[1]);
    *(__half2*)&w.y = __floats2half2_rn(r[2], r[3]);
    *(__half2*)&w.z = __floats2half2_rn(r[4], r[5]);
    *(__half2*)&w.w = __floats2half2_rn(r[6], r[7]);
    ((uint4*)((__half*)o + (size_t)row * DD))[l16] = w;
}

// ---------------- launch ------------------------------------------------------
extern "C" void kernel_launch(void* const* d_in, const int* in_sizes, int n_in,
                              void* d_out, int out_size)
{
    const int*   src     = (const int*)d_in[0];
    const int*   dst     = (const int*)d_in[1];
    const float* in_feat = (const float*)d_in[2];
    const float* W1      = (const float*)d_in[3];
    const float* b1      = (const float*)d_in[4];
    const float* W2      = (const float*)d_in[5];
    const float* b2      = (const float*)d_in[6];
    const float* ln1g    = (const float*)d_in[7];
    const float* ln1b    = (const float*)d_in[8];
    const float* ln2g    = (const float*)d_in[9];
    const float* ln2b    = (const float*)d_in[10];
    float* out = (float*)d_out;

    int E = in_sizes[0];
    int n = in_sizes[2] / DD;

    __half *t, *xw;
    float *rout, *rin;
    int *deg, *rowptr, *cursor, *csrsrc, *bsums;
    cudaGetSymbolAddress((void**)&t,      g_t);
    cudaGetSymbolAddress((void**)&xw,     g_xw);
    cudaGetSymbolAddress((void**)&rout,   g_rout);
    cudaGetSymbolAddress((void**)&rin,    g_rin);
    cudaGetSymbolAddress((void**)&deg,    g_deg);
    cudaGetSymbolAddress((void**)&rowptr, g_rowptr);
    cudaGetSymbolAddress((void**)&cursor, g_cursor);
    cudaGetSymbolAddress((void**)&csrsrc, g_csrsrc);
    cudaGetSymbolAddress((void**)&bsums,  g_bsums);
    int* degout = deg;
    int* degin  = deg + NMAX;

    const int TB = 256;
    int gridE    = (E + TB - 1) / TB;
    int gridRow  = (n + 15) / 16;
    int gridGemm = (n + 127) / 128;
    int gridScan = (n + 1023) / 1024;

    cudaMemsetAsync(deg, 0, 2 * NMAX * sizeof(int));
    degree_kernel<<<gridE, TB>>>(src, dst, degout, degin, E);
    scan_block_kernel<<<gridScan, 256>>>(degin, rowptr, bsums, n);
    scan_spine_kernel<<<1, 128>>>(bsums, gridScan);
    scan_add_kernel<<<gridScan, 256>>>(rowptr, cursor, bsums, degout, degin, rout, rin, n, E);
    csr_fill_kernel<<<gridE, TB>>>(src, dst, cursor, csrsrc, E);

    // ---- conv1 (A fp32, rout scale in GEMM)
    gemm_tf32_kernel<float><<<gridGemm, TB>>>(in_feat, W1, rout, xw, n);
    agg_kernel<true, __half><<<gridRow, TB>>>(rowptr, csrsrc, xw, rin, b1, in_feat,
                                              ln1g, ln1b, rout, t, n);

    // ---- conv2 (A fp16, already rout-scaled)
    gemm_tf32_kernel<__half><<<gridGemm, TB>>>(t, W2, nullptr, xw, n);
    agg_kernel<true, __half><<<gridRow, TB>>>(rowptr, csrsrc, xw, rin, b2, in_feat,
                                              ln2g, ln2b, rout, t, n);

    // ---- conv3
    gemm_tf32_kernel<__half><<<gridGemm, TB>>>(t, W2, nullptr, xw, n);
    agg_kernel<false, float><<<gridRow, TB>>>(rowptr, csrsrc, xw, rin, b2, in_feat,
                                              nullptr, nullptr, nullptr, out, n);
}

// round 8
// speedup vs baseline: 1.1459x; 1.0777x over previous
#include <cuda_runtime.h>
#include <cuda_fp16.h>
#include <cstdint>

#define DD 128
#define NMAX 100000
#define EMAX 1600000
#define RESC 0.2f
#define LNEPS 1e-5f

// ---------------- scratch (static device globals; no allocs allowed) --------
__device__ __half g_t[NMAX * DD];      // GEMM input (LN'd features), fp16
__device__ __half g_xw[NMAX * DD];     // GEMM output (pre-aggregation), fp16
__device__ __half g_w1t[DD * DD];      // W1^T fp16  [n][k]
__device__ __half g_w2t[DD * DD];      // W2^T fp16  [n][k]
__device__ float  g_rout[NMAX];
__device__ float  g_rin[NMAX];
__device__ int    g_deg[2 * NMAX];     // [0,N)=degout, [N,2N)=degin
__device__ int    g_rowptr[NMAX + 1];
__device__ int    g_cursor[NMAX];
__device__ int    g_csrsrc[EMAX];
__device__ int    g_bsums[256];

// ---------------- degree (int) ----------------------------------------------
__global__ void degree_kernel(const int* __restrict__ src, const int* __restrict__ dst,
                              int* __restrict__ dout, int* __restrict__ din, int e) {
    int i = blockIdx.x * blockDim.x + threadIdx.x;
    if (i < e) {
        atomicAdd(dout + src[i], 1);
        atomicAdd(din + dst[i], 1);
    }
}

// ---------------- weight transpose + fp16 convert ----------------------------
// Wt[n*128+k] = (half) W[k*128+n]; handles W1 and W2 in one launch.
__global__ void wt_kernel(const float* __restrict__ W1, const float* __restrict__ W2,
                          __half* __restrict__ W1t, __half* __restrict__ W2t) {
    int idx = blockIdx.x * blockDim.x + threadIdx.x;  // 0..32767
    int which = idx >> 14;
    int i = idx & 16383;
    int nrow = i >> 7;   // n
    int k = i & 127;
    const float* W = which ? W2 : W1;
    __half* Wt = which ? W2t : W1t;
    Wt[nrow * DD + k] = __float2half_rn(__ldg(W + k * DD + nrow));
}

// ---------------- exclusive scan over degin ----------------------------------
__global__ void scan_block_kernel(const int* __restrict__ in, int* __restrict__ out,
                                  int* __restrict__ bsums, int n) {
    __shared__ int wsum[8];
    int t = threadIdx.x;
    int lane = t & 31, wid = t >> 5;
    int base = blockIdx.x * 1024 + t * 4;

    int v0 = (base + 0 < n) ? in[base + 0] : 0;
    int v1 = (base + 1 < n) ? in[base + 1] : 0;
    int v2 = (base + 2 < n) ? in[base + 2] : 0;
    int v3 = (base + 3 < n) ? in[base + 3] : 0;
    int tsum = v0 + v1 + v2 + v3;

    int x = tsum;
#pragma unroll
    for (int o = 1; o < 32; o <<= 1) {
        int y = __shfl_up_sync(0xFFFFFFFFu, x, o);
        if (lane >= o) x += y;
    }
    if (lane == 31) wsum[wid] = x;
    __syncthreads();
    if (wid == 0) {
        int w = (lane < 8) ? wsum[lane] : 0;
        int orig = w;
#pragma unroll
        for (int o = 1; o < 8; o <<= 1) {
            int y = __shfl_up_sync(0xFFFFFFFFu, w, o);
            if (lane >= o) w += y;
        }
        if (lane < 8) wsum[lane] = w - orig;
    }
    __syncthreads();

    int texcl = wsum[wid] + x - tsum;
    if (base + 0 < n) out[base + 0] = texcl;
    if (base + 1 < n) out[base + 1] = texcl + v0;
    if (base + 2 < n) out[base + 2] = texcl + v0 + v1;
    if (base + 3 < n) out[base + 3] = texcl + v0 + v1 + v2;
    if (t == 255) bsums[blockIdx.x] = wsum[7] + x;
}

// single-warp spine: exclusive scan of up to 128 block sums
__global__ void scan_spine_kernel(int* __restrict__ bsums, int nb) {
    int lane = threadIdx.x;  // 32 threads
    int base = lane * 4;
    int v[4];
#pragma unroll
    for (int i = 0; i < 4; i++) v[i] = (base + i < nb) ? bsums[base + i] : 0;
    int tsum = v[0] + v[1] + v[2] + v[3];
    int x = tsum;
#pragma unroll
    for (int o = 1; o < 32; o <<= 1) {
        int y = __shfl_up_sync(0xFFFFFFFFu, x, o);
        if (lane >= o) x += y;
    }
    int excl = x - tsum;
    int run = excl;
#pragma unroll
    for (int i = 0; i < 4; i++) {
        if (base + i < nb) bsums[base + i] = run;
        run += v[i];
    }
}

// fused: rowptr += spine; cursor = rowptr; rout/rin = rsqrt(max(deg,1))
__global__ void scan_add_kernel(int* __restrict__ out, int* __restrict__ cursor,
                                const int* __restrict__ bsums,
                                const int* __restrict__ degout, const int* __restrict__ degin,
                                float* __restrict__ rout, float* __restrict__ rin,
                                int n, int e) {
    int base = blockIdx.x * 1024 + threadIdx.x * 4;
    int add = bsums[blockIdx.x];
#pragma unroll
    for (int i = 0; i < 4; i++) {
        int idx = base + i;
        if (idx < n) {
            int v = out[idx] + add;
            out[idx] = v;
            cursor[idx] = v;
            rout[idx] = rsqrtf((float)max(degout[idx], 1));
            rin[idx]  = rsqrtf((float)max(degin[idx], 1));
        }
    }
    if (blockIdx.x == 0 && threadIdx.x == 0) out[n] = e;
}

__global__ void csr_fill_kernel(const int* __restrict__ src, const int* __restrict__ dst,
                                int* __restrict__ cursor, int* __restrict__ csr, int e) {
    int i = blockIdx.x * blockDim.x + threadIdx.x;
    if (i < e) {
        int p = atomicAdd(cursor + dst[i], 1);
        csr[p] = src[i];
    }
}

// ---------------- FP16 tensor-core GEMM (m16n8k16), fp16 output --------------
// C[n,128] = (rs ? diag(rs) : I) A[n,128] @ W[128,128],  Wt = W^T fp16 [n][k]
// 128x128 block tile, 256 threads (8 warps: wm=wrp&3 rows, wn=wrp>>2 cols).
// smem rows padded to 24 halves (12 words) for conflict-free fragment loads.
#define SAH 24

__device__ __forceinline__ uint4 lda8(const __half* p, float sc) {
    (void)sc;
    return *(const uint4*)p;  // 8 halves
}
__device__ __forceinline__ uint4 lda8(const float* p, float sc) {
    float4 f0 = *(const float4*)p;
    float4 f1 = *(const float4*)(p + 4);
    uint4 u;
    *(__half2*)&u.x = __floats2half2_rn(f0.x * sc, f0.y * sc);
    *(__half2*)&u.y = __floats2half2_rn(f0.z * sc, f0.w * sc);
    *(__half2*)&u.z = __floats2half2_rn(f1.x * sc, f1.y * sc);
    *(__half2*)&u.w = __floats2half2_rn(f1.z * sc, f1.w * sc);
    return u;
}

template <typename AT>
__global__ __launch_bounds__(256) void gemm_f16_kernel(
    const AT* __restrict__ A, const __half* __restrict__ Wt,
    const float* __restrict__ rs, __half* __restrict__ C, int n)
{
    __shared__ __half sA[2][128 * SAH];
    __shared__ __half sW[2][128 * SAH];

    int tid = threadIdx.x;
    int lane = tid & 31;
    int wrp = tid >> 5;
    int wm = wrp & 3;        // rows wm*32
    int wn = wrp >> 2;       // cols wn*64
    int tig = lane & 3;
    int gid = lane >> 2;
    int row0 = blockIdx.x * 128;

    // staging: thread handles (srow = tid>>1, koff = (tid&1)*8)
    int srow = tid >> 1;
    int koff = (tid & 1) << 3;

    int grow = row0 + srow;
    bool rok = grow < n;
    float sc = 1.0f;
    if (rs != nullptr && rok) sc = __ldg(rs + grow);
    const AT* Ap = A + (size_t)grow * DD + koff;
    const __half* Wp = Wt + (size_t)srow * DD + koff;  // srow = n index

    float acc[2][8][4];
#pragma unroll
    for (int i = 0; i < 2; i++)
#pragma unroll
        for (int j = 0; j < 8; j++)
#pragma unroll
            for (int k = 0; k < 4; k++) acc[i][j][k] = 0.0f;

    uint4 av = make_uint4(0, 0, 0, 0);
    if (rok) av = lda8(Ap, sc);
    uint4 wv = *(const uint4*)Wp;
    *(uint4*)&sA[0][srow * SAH + koff] = av;
    *(uint4*)&sW[0][srow * SAH + koff] = wv;
    __syncthreads();

#pragma unroll
    for (int s = 0; s < 8; s++) {
        int cur = s & 1;
        if (s < 7) {
            int kb = (s + 1) * 16;
            av = make_uint4(0, 0, 0, 0);
            if (rok) av = lda8(Ap + kb, sc);
            wv = *(const uint4*)(Wp + kb);
        }

        const uint32_t* pA = (const uint32_t*)&sA[cur][0];
        const uint32_t* pW = (const uint32_t*)&sW[cur][0];
        // word stride per row = SAH/2 = 12
        uint32_t af[2][4];
#pragma unroll
        for (int mt = 0; mt < 2; mt++) {
            int rb = wm * 32 + mt * 16 + gid;
            af[mt][0] = pA[rb * 12 + tig];
            af[mt][1] = pA[(rb + 8) * 12 + tig];
            af[mt][2] = pA[rb * 12 + tig + 4];
            af[mt][3] = pA[(rb + 8) * 12 + tig + 4];
        }
#pragma unroll
        for (int nt = 0; nt < 8; nt++) {
            int cb = wn * 64 + nt * 8 + gid;
            uint32_t b0 = pW[cb * 12 + tig];
            uint32_t b1 = pW[cb * 12 + tig + 4];
#pragma unroll
            for (int mt = 0; mt < 2; mt++) {
                asm volatile(
                    "mma.sync.aligned.m16n8k16.row.col.f32.f16.f16.f32 "
                    "{%0,%1,%2,%3}, {%4,%5,%6,%7}, {%8,%9}, {%0,%1,%2,%3};"
                    : "+f"(acc[mt][nt][0]), "+f"(acc[mt][nt][1]),
                      "+f"(acc[mt][nt][2]), "+f"(acc[mt][nt][3])
                    : "r"(af[mt][0]), "r"(af[mt][1]), "r"(af[mt][2]), "r"(af[mt][3]),
                      "r"(b0), "r"(b1));
            }
        }

        if (s < 7) {
            int nb = cur ^ 1;
            *(uint4*)&sA[nb][srow * SAH + koff] = av;
            *(uint4*)&sW[nb][srow * SAH + koff] = wv;
            __syncthreads();
        }
    }

    // writeout (fp16): c0,c1 -> (row gid, col tig*2), c2,c3 -> (row gid+8)
#pragma unroll
    for (int mt = 0; mt < 2; mt++) {
        int r0 = row0 + wm * 32 + mt * 16 + gid;
        int r1 = r0 + 8;
#pragma unroll
        for (int nt = 0; nt < 8; nt++) {
            int col = wn * 64 + nt * 8 + tig * 2;
            if (r0 < n)
                *(__half2*)(C + (size_t)r0 * DD + col) =
                    __floats2half2_rn(acc[mt][nt][0], acc[mt][nt][1]);
            if (r1 < n)
                *(__half2*)(C + (size_t)r1 * DD + col) =
                    __floats2half2_rn(acc[mt][nt][2], acc[mt][nt][3]);
        }
    }
}

// ---------------- fused CSR aggregate: half-warp per row, uint4 loads --------
__device__ __forceinline__ void acc_u4(uint4 u, float* a) {
    float2 p0 = __half22float2(*(const __half2*)&u.x);
    float2 p1 = __half22float2(*(const __half2*)&u.y);
    float2 p2 = __half22float2(*(const __half2*)&u.z);
    float2 p3 = __half22float2(*(const __half2*)&u.w);
    a[0] += p0.x; a[1] += p0.y; a[2] += p1.x; a[3] += p1.y;
    a[4] += p2.x; a[5] += p2.y; a[6] += p3.x; a[7] += p3.y;
}

template <bool DO_LN, typename OT>
__global__ void agg_kernel(const int* __restrict__ rowptr, const int* __restrict__ csr,
                           const __half* __restrict__ xw, const float* __restrict__ rin,
                           const float* __restrict__ bias, const float* __restrict__ feat,
                           const float* __restrict__ lng, const float* __restrict__ lnb,
                           const float* __restrict__ rout, OT* __restrict__ o, int n)
{
    int row = blockIdx.x * 16 + (threadIdx.x >> 4);
    if (row >= n) return;
    int l16 = threadIdx.x & 15;

    int beg = __ldg(rowptr + row);
    int end = __ldg(rowptr + row + 1);

    const uint4* xwv = (const uint4*)xw + l16;
    float a[8] = {0.f, 0.f, 0.f, 0.f, 0.f, 0.f, 0.f, 0.f};

    int e = beg;
    for (; e + 8 <= end; e += 8) {
        int s[8];
#pragma unroll
        for (int q = 0; q < 8; q++) s[q] = __ldg(csr + e + q);
        uint4 u[8];
#pragma unroll
        for (int q = 0; q < 8; q++) u[q] = __ldg(xwv + (size_t)s[q] * 16);
#pragma unroll
        for (int q = 0; q < 8; q++) acc_u4(u[q], a);
    }
    if (e + 4 <= end) {
        int s[4];
#pragma unroll
        for (int q = 0; q < 4; q++) s[q] = __ldg(csr + e + q);
        uint4 u[4];
#pragma unroll
        for (int q = 0; q < 4; q++) u[q] = __ldg(xwv + (size_t)s[q] * 16);
#pragma unroll
        for (int q = 0; q < 4; q++) acc_u4(u[q], a);
        e += 4;
    }
    if (e + 2 <= end) {
        int s0 = __ldg(csr + e), s1 = __ldg(csr + e + 1);
        uint4 u0 = __ldg(xwv + (size_t)s0 * 16);
        uint4 u1 = __ldg(xwv + (size_t)s1 * 16);
        acc_u4(u0, a);
        acc_u4(u1, a);
        e += 2;
    }
    if (e < end) {
        int s0 = __ldg(csr + e);
        acc_u4(__ldg(xwv + (size_t)s0 * 16), a);
    }

    float s = __ldg(rin + row);
    float4 b0 = ((const float4*)bias)[l16 * 2];
    float4 b1 = ((const float4*)bias)[l16 * 2 + 1];
    float4 f0 = __ldg((const float4*)feat + (size_t)row * 32 + l16 * 2);
    float4 f1 = __ldg((const float4*)feat + (size_t)row * 32 + l16 * 2 + 1);
    float h[8];
    h[0] = fmaf(a[0], s, b0.x) + RESC * f0.x;
    h[1] = fmaf(a[1], s, b0.y) + RESC * f0.y;
    h[2] = fmaf(a[2], s, b0.z) + RESC * f0.z;
    h[3] = fmaf(a[3], s, b0.w) + RESC * f0.w;
    h[4] = fmaf(a[4], s, b1.x) + RESC * f1.x;
    h[5] = fmaf(a[5], s, b1.y) + RESC * f1.y;
    h[6] = fmaf(a[6], s, b1.z) + RESC * f1.z;
    h[7] = fmaf(a[7], s, b1.w) + RESC * f1.w;

    if (!DO_LN) {
        float* op = (float*)o + (size_t)row * DD + l16 * 8;
        *(float4*)op = make_float4(h[0], h[1], h[2], h[3]);
        *(float4*)(op + 4) = make_float4(h[4], h[5], h[6], h[7]);
        return;
    }

    float sum = 0.f;
#pragma unroll
    for (int q = 0; q < 8; q++) sum += h[q];
#pragma unroll
    for (int off = 8; off > 0; off >>= 1) sum += __shfl_xor_sync(0xFFFFFFFFu, sum, off);
    float mu = sum * (1.0f / 128.0f);

    float d[8], sq = 0.f;
#pragma unroll
    for (int q = 0; q < 8; q++) { d[q] = h[q] - mu; sq += d[q] * d[q]; }
#pragma unroll
    for (int off = 8; off > 0; off >>= 1) sq += __shfl_xor_sync(0xFFFFFFFFu, sq, off);
    float inv = rsqrtf(sq * (1.0f / 128.0f) + LNEPS);

    float ro = __ldg(rout + row);
    float4 g0 = ((const float4*)lng)[l16 * 2];
    float4 g1 = ((const float4*)lng)[l16 * 2 + 1];
    float4 lb0 = ((const float4*)lnb)[l16 * 2];
    float4 lb1 = ((const float4*)lnb)[l16 * 2 + 1];
    float gg[8] = {g0.x, g0.y, g0.z, g0.w, g1.x, g1.y, g1.z, g1.w};
    float lb[8] = {lb0.x, lb0.y, lb0.z, lb0.w, lb1.x, lb1.y, lb1.z, lb1.w};

    float r[8];
#pragma unroll
    for (int q = 0; q < 8; q++)
        r[q] = fmaxf(fmaf(d[q] * inv, gg[q], lb[q]), 0.0f) * ro;

    uint4 w;
    *(__half2*)&w.x = __floats2half2_rn(r[0], r[1]);
    *(__half2*)&w.y = __floats2half2_rn(r[2], r[3]);
    *(__half2*)&w.z = __floats2half2_rn(r[4], r[5]);
    *(__half2*)&w.w = __floats2half2_rn(r[6], r[7]);
    ((uint4*)((__half*)o + (size_t)row * DD))[l16] = w;
}

// ---------------- launch ------------------------------------------------------
extern "C" void kernel_launch(void* const* d_in, const int* in_sizes, int n_in,
                              void* d_out, int out_size)
{
    const int*   src     = (const int*)d_in[0];
    const int*   dst     = (const int*)d_in[1];
    const float* in_feat = (const float*)d_in[2];
    const float* W1      = (const float*)d_in[3];
    const float* b1      = (const float*)d_in[4];
    const float* W2      = (const float*)d_in[5];
    const float* b2      = (const float*)d_in[6];
    const float* ln1g    = (const float*)d_in[7];
    const float* ln1b    = (const float*)d_in[8];
    const float* ln2g    = (const float*)d_in[9];
    const float* ln2b    = (const float*)d_in[10];
    float* out = (float*)d_out;

    int E = in_sizes[0];
    int n = in_sizes[2] / DD;

    __half *t, *xw, *w1t, *w2t;
    float *rout, *rin;
    int *deg, *rowptr, *cursor, *csrsrc, *bsums;
    cudaGetSymbolAddress((void**)&t,      g_t);
    cudaGetSymbolAddress((void**)&xw,     g_xw);
    cudaGetSymbolAddress((void**)&w1t,    g_w1t);
    cudaGetSymbolAddress((void**)&w2t,    g_w2t);
    cudaGetSymbolAddress((void**)&rout,   g_rout);
    cudaGetSymbolAddress((void**)&rin,    g_rin);
    cudaGetSymbolAddress((void**)&deg,    g_deg);
    cudaGetSymbolAddress((void**)&rowptr, g_rowptr);
    cudaGetSymbolAddress((void**)&cursor, g_cursor);
    cudaGetSymbolAddress((void**)&csrsrc, g_csrsrc);
    cudaGetSymbolAddress((void**)&bsums,  g_bsums);
    int* degout = deg;
    int* degin  = deg + NMAX;

    const int TB = 256;
    int gridE    = (E + TB - 1) / TB;
    int gridRow  = (n + 15) / 16;
    int gridGemm = (n + 127) / 128;
    int gridScan = (n + 1023) / 1024;

    cudaMemsetAsync(deg, 0, 2 * NMAX * sizeof(int));
    wt_kernel<<<128, 256>>>(W1, W2, w1t, w2t);
    degree_kernel<<<gridE, TB>>>(src, dst, degout, degin, E);
    scan_block_kernel<<<gridScan, 256>>>(degin, rowptr, bsums, n);
    scan_spine_kernel<<<1, 32>>>(bsums, gridScan);
    scan_add_kernel<<<gridScan, 256>>>(rowptr, cursor, bsums, degout, degin, rout, rin, n, E);
    csr_fill_kernel<<<gridE, TB>>>(src, dst, cursor, csrsrc, E);

    // ---- conv1 (A fp32, rout scale folded into staging)
    gemm_f16_kernel<float><<<gridGemm, TB>>>(in_feat, w1t, rout, xw, n);
    agg_kernel<true, __half><<<gridRow, TB>>>(rowptr, csrsrc, xw, rin, b1, in_feat,
                                              ln1g, ln1b, rout, t, n);

    // ---- conv2 (A fp16, already rout-scaled by LN epilogue)
    gemm_f16_kernel<__half><<<gridGemm, TB>>>(t, w2t, nullptr, xw, n);
    agg_kernel<true, __half><<<gridRow, TB>>>(rowptr, csrsrc, xw, rin, b2, in_feat,
                                              ln2g, ln2b, rout, t, n);

    // ---- conv3
    gemm_f16_kernel<__half><<<gridGemm, TB>>>(t, w2t, nullptr, xw, n);
    agg_kernel<false, float><<<gridRow, TB>>>(rowptr, csrsrc, xw, rin, b2, in_feat,
                                              nullptr, nullptr, nullptr, out, n);
}

// round 9
// speedup vs baseline: 1.1918x; 1.0400x over previous
#include <cuda_runtime.h>
#include <cuda_fp16.h>
#include <cstdint>

#define DD 128
#define NMAX 100000
#define EMAX 1600000
#define RESC 0.2f
#define LNEPS 1e-5f

// ---------------- scratch (static device globals; no allocs allowed) --------
__device__ __half g_t[NMAX * DD];      // GEMM input (LN'd features), fp16
__device__ __half g_xw[NMAX * DD];     // GEMM output (pre-aggregation), fp16
__device__ __half g_f16[NMAX * DD];    // in_feat converted to fp16 (residual)
__device__ __half g_w1t[DD * DD];      // W1^T fp16  [n][k]
__device__ __half g_w2t[DD * DD];      // W2^T fp16  [n][k]
__device__ float  g_rout[NMAX];
__device__ float  g_rin[NMAX];
// blob: [0, NMAX) ull = deg (2*NMAX ints: degout, degin), [NMAX, NMAX+128) = scan states
__device__ unsigned long long g_blob[NMAX + 128];
__device__ int    g_rowptr[NMAX + 1];
__device__ int    g_cursor[NMAX];
__device__ int    g_csrsrc[EMAX];

// ---------------- fused prep: degree + weight transpose + feat->fp16 --------
__global__ void prep_kernel(const int* __restrict__ src, const int* __restrict__ dst,
                            int* __restrict__ dout, int* __restrict__ din,
                            const float* __restrict__ W1, const float* __restrict__ W2,
                            __half* __restrict__ W1t, __half* __restrict__ W2t,
                            const float* __restrict__ feat, __half* __restrict__ feat16,
                            int e, int n, int gridE) {
    int b = blockIdx.x;
    if (b < gridE) {
        int i = b * 256 + threadIdx.x;
        if (i < e) {
            atomicAdd(dout + src[i], 1);
            atomicAdd(din + dst[i], 1);
        }
    } else if (b < gridE + 128) {
        int idx = (b - gridE) * 256 + threadIdx.x;  // 0..32767
        int which = idx >> 14;
        int i = idx & 16383;
        int nrow = i >> 7;
        int k = i & 127;
        const float* W = which ? W2 : W1;
        __half* Wt = which ? W2t : W1t;
        Wt[nrow * DD + k] = __float2half_rn(__ldg(W + k * DD + nrow));
    } else {
        int i = (b - gridE - 128) * 256 + threadIdx.x;  // converts 8 floats
        if (i < n * 16) {
            const float4* fp = (const float4*)feat + (size_t)i * 2;
            float4 f0 = __ldg(fp);
            float4 f1 = __ldg(fp + 1);
            uint4 u;
            *(__half2*)&u.x = __floats2half2_rn(f0.x, f0.y);
            *(__half2*)&u.y = __floats2half2_rn(f0.z, f0.w);
            *(__half2*)&u.z = __floats2half2_rn(f1.x, f1.y);
            *(__half2*)&u.w = __floats2half2_rn(f1.z, f1.w);
            ((uint4*)feat16)[i] = u;
        }
    }
}

// ---------------- single-pass decoupled-lookback scan ------------------------
// Exclusive scan of degin -> rowptr; also emits cursor, rout, rin, rowptr[n]=E.
// state[b]: (flag<<32)|value; flag 1 = block aggregate, 2 = inclusive prefix.
__global__ __launch_bounds__(256) void scan_lookback_kernel(
    const int* __restrict__ degin, const int* __restrict__ degout,
    unsigned long long* __restrict__ state,
    int* __restrict__ rowptr, int* __restrict__ cursor,
    float* __restrict__ rout, float* __restrict__ rin,
    int n, int e)
{
    __shared__ int wsum[8];
    __shared__ int sExcl;
    int b = blockIdx.x;
    int t = threadIdx.x;
    int lane = t & 31, wid = t >> 5;
    int base = b * 1024 + t * 4;

    int v0 = (base + 0 < n) ? degin[base + 0] : 0;
    int v1 = (base + 1 < n) ? degin[base + 1] : 0;
    int v2 = (base + 2 < n) ? degin[base + 2] : 0;
    int v3 = (base + 3 < n) ? degin[base + 3] : 0;
    int tsum = v0 + v1 + v2 + v3;

    int x = tsum;
#pragma unroll
    for (int o = 1; o < 32; o <<= 1) {
        int y = __shfl_up_sync(0xFFFFFFFFu, x, o);
        if (lane >= o) x += y;
    }
    if (lane == 31) wsum[wid] = x;
    __syncthreads();

    if (wid == 0) {
        int w = (lane < 8) ? wsum[lane] : 0;
        int orig = w;
#pragma unroll
        for (int o = 1; o < 8; o <<= 1) {
            int y = __shfl_up_sync(0xFFFFFFFFu, w, o);
            if (lane >= o) w += y;
        }
        if (lane < 8) wsum[lane] = w - orig;
        int total = __shfl_sync(0xFFFFFFFFu, w, 7);

        // publish aggregate (block 0 publishes full prefix directly)
        if (lane == 0) {
            unsigned long long pub =
                ((unsigned long long)(b == 0 ? 2u : 1u) << 32) | (unsigned)total;
            atomicExch(&state[b], pub);
        }

        // warp-parallel lookback
        int excl = 0;
        if (b > 0) {
            int p = b - 1;
            while (true) {
                int idx = p - lane;
                unsigned long long v;
                if (idx >= 0) {
                    do { v = atomicAdd(&state[idx], 0ULL); } while ((v >> 32) == 0);
                } else {
                    v = (2ULL << 32);  // sentinel: prefix 0
                }
                unsigned flag = (unsigned)(v >> 32);
                int val = (int)(v & 0xFFFFFFFFu);
                unsigned pmask = __ballot_sync(0xFFFFFFFFu, flag == 2u);
                int c;
                if (pmask) {
                    int L = __ffs(pmask) - 1;
                    c = (lane <= L) ? val : 0;
                } else {
                    c = val;
                }
#pragma unroll
                for (int o = 16; o > 0; o >>= 1) c += __shfl_xor_sync(0xFFFFFFFFu, c, o);
                excl += c;
                if (pmask) break;
                p -= 32;
            }
            if (lane == 0)
                atomicExch(&state[b], (2ULL << 32) | (unsigned)(excl + total));
        }
        if (lane == 0) sExcl = excl;
    }
    __syncthreads();

    int texcl = wsum[wid] + x - tsum + sExcl;
    int run = texcl;
    int dv[4] = {v0, v1, v2, v3};
#pragma unroll
    for (int i = 0; i < 4; i++) {
        int idx = base + i;
        if (idx < n) {
            rowptr[idx] = run;
            cursor[idx] = run;
            rout[idx] = rsqrtf((float)max(degout[idx], 1));
            rin[idx]  = rsqrtf((float)max(dv[i], 1));
        }
        run += dv[i];
    }
    if (b == 0 && t == 0) rowptr[n] = e;
}

__global__ void csr_fill_kernel(const int* __restrict__ src, const int* __restrict__ dst,
                                int* __restrict__ cursor, int* __restrict__ csr, int e) {
    int i = blockIdx.x * blockDim.x + threadIdx.x;
    if (i < e) {
        int p = atomicAdd(cursor + dst[i], 1);
        csr[p] = src[i];
    }
}

// ---------------- FP16 tensor-core GEMM (m16n8k16), fp16 output --------------
#define SAH 24

__device__ __forceinline__ uint4 lda8(const __half* p, float sc) {
    (void)sc;
    return *(const uint4*)p;
}
__device__ __forceinline__ uint4 lda8(const float* p, float sc) {
    float4 f0 = *(const float4*)p;
    float4 f1 = *(const float4*)(p + 4);
    uint4 u;
    *(__half2*)&u.x = __floats2half2_rn(f0.x * sc, f0.y * sc);
    *(__half2*)&u.y = __floats2half2_rn(f0.z * sc, f0.w * sc);
    *(__half2*)&u.z = __floats2half2_rn(f1.x * sc, f1.y * sc);
    *(__half2*)&u.w = __floats2half2_rn(f1.z * sc, f1.w * sc);
    return u;
}

template <typename AT>
__global__ __launch_bounds__(256) void gemm_f16_kernel(
    const AT* __restrict__ A, const __half* __restrict__ Wt,
    const float* __restrict__ rs, __half* __restrict__ C, int n)
{
    __shared__ __half sA[2][128 * SAH];
    __shared__ __half sW[2][128 * SAH];

    int tid = threadIdx.x;
    int lane = tid & 31;
    int wrp = tid >> 5;
    int wm = wrp & 3;
    int wn = wrp >> 2;
    int tig = lane & 3;
    int gid = lane >> 2;
    int row0 = blockIdx.x * 128;

    int srow = tid >> 1;
    int koff = (tid & 1) << 3;

    int grow = row0 + srow;
    bool rok = grow < n;
    float sc = 1.0f;
    if (rs != nullptr && rok) sc = __ldg(rs + grow);
    const AT* Ap = A + (size_t)grow * DD + koff;
    const __half* Wp = Wt + (size_t)srow * DD + koff;

    float acc[2][8][4];
#pragma unroll
    for (int i = 0; i < 2; i++)
#pragma unroll
        for (int j = 0; j < 8; j++)
#pragma unroll
            for (int k = 0; k < 4; k++) acc[i][j][k] = 0.0f;

    uint4 av = make_uint4(0, 0, 0, 0);
    if (rok) av = lda8(Ap, sc);
    uint4 wv = *(const uint4*)Wp;
    *(uint4*)&sA[0][srow * SAH + koff] = av;
    *(uint4*)&sW[0][srow * SAH + koff] = wv;
    __syncthreads();

#pragma unroll
    for (int s = 0; s < 8; s++) {
        int cur = s & 1;
        if (s < 7) {
            int kb = (s + 1) * 16;
            av = make_uint4(0, 0, 0, 0);
            if (rok) av = lda8(Ap + kb, sc);
            wv = *(const uint4*)(Wp + kb);
        }

        const uint32_t* pA = (const uint32_t*)&sA[cur][0];
        const uint32_t* pW = (const uint32_t*)&sW[cur][0];
        uint32_t af[2][4];
#pragma unroll
        for (int mt = 0; mt < 2; mt++) {
            int rb = wm * 32 + mt * 16 + gid;
            af[mt][0] = pA[rb * 12 + tig];
            af[mt][1] = pA[(rb + 8) * 12 + tig];
            af[mt][2] = pA[rb * 12 + tig + 4];
            af[mt][3] = pA[(rb + 8) * 12 + tig + 4];
        }
#pragma unroll
        for (int nt = 0; nt < 8; nt++) {
            int cb = wn * 64 + nt * 8 + gid;
            uint32_t b0 = pW[cb * 12 + tig];
            uint32_t b1 = pW[cb * 12 + tig + 4];
#pragma unroll
            for (int mt = 0; mt < 2; mt++) {
                asm volatile(
                    "mma.sync.aligned.m16n8k16.row.col.f32.f16.f16.f32 "
                    "{%0,%1,%2,%3}, {%4,%5,%6,%7}, {%8,%9}, {%0,%1,%2,%3};"
                    : "+f"(acc[mt][nt][0]), "+f"(acc[mt][nt][1]),
                      "+f"(acc[mt][nt][2]), "+f"(acc[mt][nt][3])
                    : "r"(af[mt][0]), "r"(af[mt][1]), "r"(af[mt][2]), "r"(af[mt][3]),
                      "r"(b0), "r"(b1));
            }
        }

        if (s < 7) {
            int nb = cur ^ 1;
            *(uint4*)&sA[nb][srow * SAH + koff] = av;
            *(uint4*)&sW[nb][srow * SAH + koff] = wv;
            __syncthreads();
        }
    }

#pragma unroll
    for (int mt = 0; mt < 2; mt++) {
        int r0 = row0 + wm * 32 + mt * 16 + gid;
        int r1 = r0 + 8;
#pragma unroll
        for (int nt = 0; nt < 8; nt++) {
            int col = wn * 64 + nt * 8 + tig * 2;
            if (r0 < n)
                *(__half2*)(C + (size_t)r0 * DD + col) =
                    __floats2half2_rn(acc[mt][nt][0], acc[mt][nt][1]);
            if (r1 < n)
                *(__half2*)(C + (size_t)r1 * DD + col) =
                    __floats2half2_rn(acc[mt][nt][2], acc[mt][nt][3]);
        }
    }
}

// ---------------- fused CSR aggregate: half-warp per row, uint4 loads --------
__device__ __forceinline__ void acc_u4(uint4 u, float* a) {
    float2 p0 = __half22float2(*(const __half2*)&u.x);
    float2 p1 = __half22float2(*(const __half2*)&u.y);
    float2 p2 = __half22float2(*(const __half2*)&u.z);
    float2 p3 = __half22float2(*(const __half2*)&u.w);
    a[0] += p0.x; a[1] += p0.y; a[2] += p1.x; a[3] += p1.y;
    a[4] += p2.x; a[5] += p2.y; a[6] += p3.x; a[7] += p3.y;
}

template <bool DO_LN, typename OT>
__global__ void agg_kernel(const int* __restrict__ rowptr, const int* __restrict__ csr,
                           const __half* __restrict__ xw, const float* __restrict__ rin,
                           const float* __restrict__ bias, const __half* __restrict__ feat16,
                           const float* __restrict__ lng, const float* __restrict__ lnb,
                           const float* __restrict__ rout, OT* __restrict__ o, int n)
{
    int row = blockIdx.x * 16 + (threadIdx.x >> 4);
    if (row >= n) return;
    int l16 = threadIdx.x & 15;

    int beg = __ldg(rowptr + row);
    int end = __ldg(rowptr + row + 1);

    const uint4* xwv = (const uint4*)xw + l16;
    float a[8] = {0.f, 0.f, 0.f, 0.f, 0.f, 0.f, 0.f, 0.f};

    int e = beg;
    for (; e + 8 <= end; e += 8) {
        int s[8];
#pragma unroll
        for (int q = 0; q < 8; q++) s[q] = __ldg(csr + e + q);
        uint4 u[8];
#pragma unroll
        for (int q = 0; q < 8; q++) u[q] = __ldg(xwv + (size_t)s[q] * 16);
#pragma unroll
        for (int q = 0; q < 8; q++) acc_u4(u[q], a);
    }
    if (e + 4 <= end) {
        int s[4];
#pragma unroll
        for (int q = 0; q < 4; q++) s[q] = __ldg(csr + e + q);
        uint4 u[4];
#pragma unroll
        for (int q = 0; q < 4; q++) u[q] = __ldg(xwv + (size_t)s[q] * 16);
#pragma unroll
        for (int q = 0; q < 4; q++) acc_u4(u[q], a);
        e += 4;
    }
    if (e + 2 <= end) {
        int s0 = __ldg(csr + e), s1 = __ldg(csr + e + 1);
        uint4 u0 = __ldg(xwv + (size_t)s0 * 16);
        uint4 u1 = __ldg(xwv + (size_t)s1 * 16);
        acc_u4(u0, a);
        acc_u4(u1, a);
        e += 2;
    }
    if (e < end) {
        int s0 = __ldg(csr + e);
        acc_u4(__ldg(xwv + (size_t)s0 * 16), a);
    }

    // residual from fp16 feat
    uint4 uf = __ldg((const uint4*)feat16 + (size_t)row * 16 + l16);
    float f[8];
    {
        float2 p0 = __half22float2(*(const __half2*)&uf.x);
        float2 p1 = __half22float2(*(const __half2*)&uf.y);
        float2 p2 = __half22float2(*(const __half2*)&uf.z);
        float2 p3 = __half22float2(*(const __half2*)&uf.w);
        f[0] = p0.x; f[1] = p0.y; f[2] = p1.x; f[3] = p1.y;
        f[4] = p2.x; f[5] = p2.y; f[6] = p3.x; f[7] = p3.y;
    }

    float s = __ldg(rin + row);
    float4 b0 = ((const float4*)bias)[l16 * 2];
    float4 b1 = ((const float4*)bias)[l16 * 2 + 1];
    float bb[8] = {b0.x, b0.y, b0.z, b0.w, b1.x, b1.y, b1.z, b1.w};
    float h[8];
#pragma unroll
    for (int q = 0; q < 8; q++) h[q] = fmaf(a[q], s, bb[q]) + RESC * f[q];

    if (!DO_LN) {
        float* op = (float*)o + (size_t)row * DD + l16 * 8;
        *(float4*)op = make_float4(h[0], h[1], h[2], h[3]);
        *(float4*)(op + 4) = make_float4(h[4], h[5], h[6], h[7]);
        return;
    }

    float sum = 0.f;
#pragma unroll
    for (int q = 0; q < 8; q++) sum += h[q];
#pragma unroll
    for (int off = 8; off > 0; off >>= 1) sum += __shfl_xor_sync(0xFFFFFFFFu, sum, off);
    float mu = sum * (1.0f / 128.0f);

    float d[8], sq = 0.f;
#pragma unroll
    for (int q = 0; q < 8; q++) { d[q] = h[q] - mu; sq += d[q] * d[q]; }
#pragma unroll
    for (int off = 8; off > 0; off >>= 1) sq += __shfl_xor_sync(0xFFFFFFFFu, sq, off);
    float inv = rsqrtf(sq * (1.0f / 128.0f) + LNEPS);

    float ro = __ldg(rout + row);
    float4 g0 = ((const float4*)lng)[l16 * 2];
    float4 g1 = ((const float4*)lng)[l16 * 2 + 1];
    float4 lb0 = ((const float4*)lnb)[l16 * 2];
    float4 lb1 = ((const float4*)lnb)[l16 * 2 + 1];
    float gg[8] = {g0.x, g0.y, g0.z, g0.w, g1.x, g1.y, g1.z, g1.w};
    float lb[8] = {lb0.x, lb0.y, lb0.z, lb0.w, lb1.x, lb1.y, lb1.z, lb1.w};

    float r[8];
#pragma unroll
    for (int q = 0; q < 8; q++)
        r[q] = fmaxf(fmaf(d[q] * inv, gg[q], lb[q]), 0.0f) * ro;

    uint4 w;
    *(__half2*)&w.x = __floats2half2_rn(r[0], r[1]);
    *(__half2*)&w.y = __floats2half2_rn(r[2], r[3]);
    *(__half2*)&w.z = __floats2half2_rn(r[4], r[5]);
    *(__half2*)&w.w = __floats2half2_rn(r[6], r[7]);
    ((uint4*)((__half*)o + (size_t)row * DD))[l16] = w;
}

// ---------------- launch ------------------------------------------------------
extern "C" void kernel_launch(void* const* d_in, const int* in_sizes, int n_in,
                              void* d_out, int out_size)
{
    const int*   src     = (const int*)d_in[0];
    const int*   dst     = (const int*)d_in[1];
    const float* in_feat = (const float*)d_in[2];
    const float* W1      = (const float*)d_in[3];
    const float* b1      = (const float*)d_in[4];
    const float* W2      = (const float*)d_in[5];
    const float* b2      = (const float*)d_in[6];
    const float* ln1g    = (const float*)d_in[7];
    const float* ln1b    = (const float*)d_in[8];
    const float* ln2g    = (const float*)d_in[9];
    const float* ln2b    = (const float*)d_in[10];
    float* out = (float*)d_out;

    int E = in_sizes[0];
    int n = in_sizes[2] / DD;

    __half *t, *xw, *f16, *w1t, *w2t;
    float *rout, *rin;
    unsigned long long* blob;
    int *rowptr, *cursor, *csrsrc;
    cudaGetSymbolAddress((void**)&t,      g_t);
    cudaGetSymbolAddress((void**)&xw,     g_xw);
    cudaGetSymbolAddress((void**)&f16,    g_f16);
    cudaGetSymbolAddress((void**)&w1t,    g_w1t);
    cudaGetSymbolAddress((void**)&w2t,    g_w2t);
    cudaGetSymbolAddress((void**)&rout,   g_rout);
    cudaGetSymbolAddress((void**)&rin,    g_rin);
    cudaGetSymbolAddress((void**)&blob,   g_blob);
    cudaGetSymbolAddress((void**)&rowptr, g_rowptr);
    cudaGetSymbolAddress((void**)&cursor, g_cursor);
    cudaGetSymbolAddress((void**)&csrsrc, g_csrsrc);
    int* degout = (int*)blob;
    int* degin  = degout + NMAX;
    unsigned long long* state = blob + NMAX;

    const int TB = 256;
    int gridE    = (E + TB - 1) / TB;
    int gridF    = (n * 16 + TB - 1) / TB;
    int gridRow  = (n + 15) / 16;
    int gridGemm = (n + 127) / 128;
    int gridScan = (n + 1023) / 1024;

    // 1: zero deg + scan states in one memset
    cudaMemsetAsync(blob, 0, (NMAX + 128) * sizeof(unsigned long long));
    // 2: fused degree + weight transpose + feat->fp16
    prep_kernel<<<gridE + 128 + gridF, TB>>>(src, dst, degout, degin, W1, W2,
                                             w1t, w2t, in_feat, f16, E, n, gridE);
    // 3: single-pass scan (+ cursor, rout, rin)
    scan_lookback_kernel<<<gridScan, 256>>>(degin, degout, state, rowptr, cursor,
                                            rout, rin, n, E);
    // 4: CSR fill
    csr_fill_kernel<<<gridE, TB>>>(src, dst, cursor, csrsrc, E);

    // 5: conv1 GEMM (A fp32, rout scale in staging)
    gemm_f16_kernel<float><<<gridGemm, TB>>>(in_feat, w1t, rout, xw, n);
    // 6: conv1 agg (+LN1)
    agg_kernel<true, __half><<<gridRow, TB>>>(rowptr, csrsrc, xw, rin, b1, f16,
                                              ln1g, ln1b, rout, t, n);

    // conv2
    gemm_f16_kernel<__half><<<gridGemm, TB>>>(t, w2t, nullptr, xw, n);
    agg_kernel<true, __half><<<gridRow, TB>>>(rowptr, csrsrc, xw, rin, b2, f16,
                                              ln2g, ln2b, rout, t, n);

    // conv3
    gemm_f16_kernel<__half><<<gridGemm, TB>>>(t, w2t, nullptr, xw, n);
    agg_kernel<false, float><<<gridRow, TB>>>(rowptr, csrsrc, xw, rin, b2, f16,
                                              nullptr, nullptr, nullptr, out, n);
}

// round 10
// speedup vs baseline: 1.2622x; 1.0591x over previous
#include <cuda_runtime.h>
#include <cuda_fp16.h>
#include <cstdint>

#define DD 128
#define NMAX 100000
#define EMAX 1600000
#define RESC 0.2f
#define LNEPS 1e-5f

// ---------------- scratch (static device globals; no allocs allowed) --------
__device__ __half g_t[NMAX * DD];      // GEMM input (LN'd features), fp16
__device__ __half g_xw[NMAX * DD];     // GEMM output (pre-aggregation), fp16
__device__ __half g_f16[NMAX * DD];    // in_feat converted to fp16 (residual)
__device__ __half g_w1t[DD * DD];      // W1^T fp16  [n][k]
__device__ __half g_w2t[DD * DD];      // W2^T fp16  [n][k]
__device__ float  g_rout[NMAX];
__device__ float  g_rin[NMAX];
__device__ unsigned long long g_blob[NMAX + 128];  // deg ints + scan states
__device__ int    g_rowptr[NMAX + 1];
__device__ int    g_cursor[NMAX];
__device__ int    g_csrsrc[EMAX];

// ---------------- fused prep: degree + weight transpose + feat->fp16 --------
__global__ void prep_kernel(const int* __restrict__ src, const int* __restrict__ dst,
                            int* __restrict__ dout, int* __restrict__ din,
                            const float* __restrict__ W1, const float* __restrict__ W2,
                            __half* __restrict__ W1t, __half* __restrict__ W2t,
                            const float* __restrict__ feat, __half* __restrict__ feat16,
                            int e, int n, int gridE) {
    int b = blockIdx.x;
    if (b < gridE) {
        int i = b * 256 + threadIdx.x;
        if (i < e) {
            atomicAdd(dout + src[i], 1);
            atomicAdd(din + dst[i], 1);
        }
    } else if (b < gridE + 128) {
        int idx = (b - gridE) * 256 + threadIdx.x;
        int which = idx >> 14;
        int i = idx & 16383;
        int nrow = i >> 7;
        int k = i & 127;
        const float* W = which ? W2 : W1;
        __half* Wt = which ? W2t : W1t;
        Wt[nrow * DD + k] = __float2half_rn(__ldg(W + k * DD + nrow));
    } else {
        int i = (b - gridE - 128) * 256 + threadIdx.x;
        if (i < n * 16) {
            const float4* fp = (const float4*)feat + (size_t)i * 2;
            float4 f0 = __ldg(fp);
            float4 f1 = __ldg(fp + 1);
            uint4 u;
            *(__half2*)&u.x = __floats2half2_rn(f0.x, f0.y);
            *(__half2*)&u.y = __floats2half2_rn(f0.z, f0.w);
            *(__half2*)&u.z = __floats2half2_rn(f1.x, f1.y);
            *(__half2*)&u.w = __floats2half2_rn(f1.z, f1.w);
            ((uint4*)feat16)[i] = u;
        }
    }
}

// ---------------- single-pass decoupled-lookback scan ------------------------
__global__ __launch_bounds__(256) void scan_lookback_kernel(
    const int* __restrict__ degin, const int* __restrict__ degout,
    unsigned long long* __restrict__ state,
    int* __restrict__ rowptr, int* __restrict__ cursor,
    float* __restrict__ rout, float* __restrict__ rin,
    int n, int e)
{
    __shared__ int wsum[8];
    __shared__ int sExcl;
    int b = blockIdx.x;
    int t = threadIdx.x;
    int lane = t & 31, wid = t >> 5;
    int base = b * 1024 + t * 4;

    int v0 = (base + 0 < n) ? degin[base + 0] : 0;
    int v1 = (base + 1 < n) ? degin[base + 1] : 0;
    int v2 = (base + 2 < n) ? degin[base + 2] : 0;
    int v3 = (base + 3 < n) ? degin[base + 3] : 0;
    int tsum = v0 + v1 + v2 + v3;

    int x = tsum;
#pragma unroll
    for (int o = 1; o < 32; o <<= 1) {
        int y = __shfl_up_sync(0xFFFFFFFFu, x, o);
        if (lane >= o) x += y;
    }
    if (lane == 31) wsum[wid] = x;
    __syncthreads();

    if (wid == 0) {
        int w = (lane < 8) ? wsum[lane] : 0;
        int orig = w;
#pragma unroll
        for (int o = 1; o < 8; o <<= 1) {
            int y = __shfl_up_sync(0xFFFFFFFFu, w, o);
            if (lane >= o) w += y;
        }
        if (lane < 8) wsum[lane] = w - orig;
        int total = __shfl_sync(0xFFFFFFFFu, w, 7);

        if (lane == 0) {
            unsigned long long pub =
                ((unsigned long long)(b == 0 ? 2u : 1u) << 32) | (unsigned)total;
            atomicExch(&state[b], pub);
        }

        int excl = 0;
        if (b > 0) {
            int p = b - 1;
            while (true) {
                int idx = p - lane;
                unsigned long long v;
                if (idx >= 0) {
                    do { v = atomicAdd(&state[idx], 0ULL); } while ((v >> 32) == 0);
                } else {
                    v = (2ULL << 32);
                }
                unsigned flag = (unsigned)(v >> 32);
                int val = (int)(v & 0xFFFFFFFFu);
                unsigned pmask = __ballot_sync(0xFFFFFFFFu, flag == 2u);
                int c;
                if (pmask) {
                    int L = __ffs(pmask) - 1;
                    c = (lane <= L) ? val : 0;
                } else {
                    c = val;
                }
#pragma unroll
                for (int o = 16; o > 0; o >>= 1) c += __shfl_xor_sync(0xFFFFFFFFu, c, o);
                excl += c;
                if (pmask) break;
                p -= 32;
            }
            if (lane == 0)
                atomicExch(&state[b], (2ULL << 32) | (unsigned)(excl + total));
        }
        if (lane == 0) sExcl = excl;
    }
    __syncthreads();

    int texcl = wsum[wid] + x - tsum + sExcl;
    int run = texcl;
    int dv[4] = {v0, v1, v2, v3};
#pragma unroll
    for (int i = 0; i < 4; i++) {
        int idx = base + i;
        if (idx < n) {
            rowptr[idx] = run;
            cursor[idx] = run;
            rout[idx] = rsqrtf((float)max(degout[idx], 1));
            rin[idx]  = rsqrtf((float)max(dv[i], 1));
        }
        run += dv[i];
    }
    if (b == 0 && t == 0) rowptr[n] = e;
}

__global__ void csr_fill_kernel(const int* __restrict__ src, const int* __restrict__ dst,
                                int* __restrict__ cursor, int* __restrict__ csr, int e) {
    int i = blockIdx.x * blockDim.x + threadIdx.x;
    if (i < e) {
        int p = atomicAdd(cursor + dst[i], 1);
        csr[p] = src[i];
    }
}

// ---------------- FP16 tensor-core GEMM v2: 64x128 tile, full-W smem ---------
// 256 threads (8 warps: wm=wrp&1 -> 32 rows, wn=wrp>>1 -> 32 cols).
// acc[2][4][4] = 32 regs/thread. W resident in smem (no staging), A double-buffered.
#define SWW 68   // W row stride in words (136 halves: 128 + 8 pad)
#define SAW 12   // A row stride in words (24 halves: 16 + 8 pad)

__device__ __forceinline__ uint2 lda4(const __half* p, float sc) {
    (void)sc;
    return *(const uint2*)p;
}
__device__ __forceinline__ uint2 lda4(const float* p, float sc) {
    float4 f = *(const float4*)p;
    uint2 u;
    *(__half2*)&u.x = __floats2half2_rn(f.x * sc, f.y * sc);
    *(__half2*)&u.y = __floats2half2_rn(f.z * sc, f.w * sc);
    return u;
}

template <typename AT>
__global__ __launch_bounds__(256) void gemm_f16_kernel(
    const AT* __restrict__ A, const __half* __restrict__ Wt,
    const float* __restrict__ rs, __half* __restrict__ C, int n)
{
    __shared__ __half sW[128 * 2 * SWW];     // [n][k], full 128x128
    __shared__ __half sA[2][64 * 2 * SAW];   // [row][k16] double-buffered

    int tid = threadIdx.x;
    int lane = tid & 31;
    int wrp = tid >> 5;
    int wm = wrp & 1;        // rows wm*32
    int wn = wrp >> 1;       // cols wn*32
    int tig = lane & 3;
    int gid = lane >> 2;
    int row0 = blockIdx.x * 64;

    // ---- load full W into smem (2048 uint4, 8 per thread)
#pragma unroll
    for (int q = 0; q < 8; q++) {
        int idx = q * 256 + tid;
        int wr = idx >> 4;
        int kb = idx & 15;
        *(uint4*)&sW[wr * 2 * SWW + kb * 8] = *(const uint4*)(Wt + wr * DD + kb * 8);
    }

    // ---- A staging: thread -> (arow = tid>>2, ak = (tid&3)*4)
    int arow = tid >> 2;
    int ak = (tid & 3) << 2;
    int grow = row0 + arow;
    bool rok = grow < n;
    float sc = 1.0f;
    if (rs != nullptr && rok) sc = __ldg(rs + grow);
    const AT* Ap = A + (size_t)grow * DD + ak;

    uint2 av = make_uint2(0, 0);
    if (rok) av = lda4(Ap, sc);
    *(uint2*)&sA[0][arow * 2 * SAW + ak] = av;
    __syncthreads();

    float acc[2][4][4];
#pragma unroll
    for (int i = 0; i < 2; i++)
#pragma unroll
        for (int j = 0; j < 4; j++)
#pragma unroll
            for (int k = 0; k < 4; k++) acc[i][j][k] = 0.0f;

#pragma unroll
    for (int s = 0; s < 8; s++) {
        int cur = s & 1;
        if (s < 7) {
            av = make_uint2(0, 0);
            if (rok) av = lda4(Ap + (s + 1) * 16, sc);
        }

        const uint32_t* pA = (const uint32_t*)&sA[cur][0];
        const uint32_t* pW = (const uint32_t*)&sW[0];
        int kw = s * 8;  // word offset into W row for this K stage

        uint32_t af[2][4];
#pragma unroll
        for (int mt = 0; mt < 2; mt++) {
            int rb = wm * 32 + mt * 16 + gid;
            af[mt][0] = pA[rb * SAW + tig];
            af[mt][1] = pA[(rb + 8) * SAW + tig];
            af[mt][2] = pA[rb * SAW + tig + 4];
            af[mt][3] = pA[(rb + 8) * SAW + tig + 4];
        }
#pragma unroll
        for (int nt = 0; nt < 4; nt++) {
            int cb = wn * 32 + nt * 8 + gid;
            uint32_t b0 = pW[cb * SWW + kw + tig];
            uint32_t b1 = pW[cb * SWW + kw + tig + 4];
#pragma unroll
            for (int mt = 0; mt < 2; mt++) {
                asm volatile(
                    "mma.sync.aligned.m16n8k16.row.col.f32.f16.f16.f32 "
                    "{%0,%1,%2,%3}, {%4,%5,%6,%7}, {%8,%9}, {%0,%1,%2,%3};"
                    : "+f"(acc[mt][nt][0]), "+f"(acc[mt][nt][1]),
                      "+f"(acc[mt][nt][2]), "+f"(acc[mt][nt][3])
                    : "r"(af[mt][0]), "r"(af[mt][1]), "r"(af[mt][2]), "r"(af[mt][3]),
                      "r"(b0), "r"(b1));
            }
        }

        if (s < 7) {
            int nb = cur ^ 1;
            *(uint2*)&sA[nb][arow * 2 * SAW + ak] = av;
            __syncthreads();
        }
    }

    // ---- writeout
#pragma unroll
    for (int mt = 0; mt < 2; mt++) {
        int r0 = row0 + wm * 32 + mt * 16 + gid;
        int r1 = r0 + 8;
#pragma unroll
        for (int nt = 0; nt < 4; nt++) {
            int col = wn * 32 + nt * 8 + tig * 2;
            if (r0 < n)
                *(__half2*)(C + (size_t)r0 * DD + col) =
                    __floats2half2_rn(acc[mt][nt][0], acc[mt][nt][1]);
            if (r1 < n)
                *(__half2*)(C + (size_t)r1 * DD + col) =
                    __floats2half2_rn(acc[mt][nt][2], acc[mt][nt][3]);
        }
    }
}

// ---------------- fused CSR aggregate: half-warp per row, uint4 loads --------
__device__ __forceinline__ void acc_u4(uint4 u, float* a) {
    float2 p0 = __half22float2(*(const __half2*)&u.x);
    float2 p1 = __half22float2(*(const __half2*)&u.y);
    float2 p2 = __half22float2(*(const __half2*)&u.z);
    float2 p3 = __half22float2(*(const __half2*)&u.w);
    a[0] += p0.x; a[1] += p0.y; a[2] += p1.x; a[3] += p1.y;
    a[4] += p2.x; a[5] += p2.y; a[6] += p3.x; a[7] += p3.y;
}

template <bool DO_LN, typename OT>
__global__ void agg_kernel(const int* __restrict__ rowptr, const int* __restrict__ csr,
                           const __half* __restrict__ xw, const float* __restrict__ rin,
                           const float* __restrict__ bias, const __half* __restrict__ feat16,
                           const float* __restrict__ lng, const float* __restrict__ lnb,
                           const float* __restrict__ rout, OT* __restrict__ o, int n)
{
    int row = blockIdx.x * 16 + (threadIdx.x >> 4);
    if (row >= n) return;
    int l16 = threadIdx.x & 15;

    int beg = __ldg(rowptr + row);
    int end = __ldg(rowptr + row + 1);

    const uint4* xwv = (const uint4*)xw + l16;
    float a[8] = {0.f, 0.f, 0.f, 0.f, 0.f, 0.f, 0.f, 0.f};

    int e = beg;
    for (; e + 8 <= end; e += 8) {
        int s[8];
#pragma unroll
        for (int q = 0; q < 8; q++) s[q] = __ldg(csr + e + q);
        uint4 u[8];
#pragma unroll
        for (int q = 0; q < 8; q++) u[q] = __ldg(xwv + (size_t)s[q] * 16);
#pragma unroll
        for (int q = 0; q < 8; q++) acc_u4(u[q], a);
    }
    if (e + 4 <= end) {
        int s[4];
#pragma unroll
        for (int q = 0; q < 4; q++) s[q] = __ldg(csr + e + q);
        uint4 u[4];
#pragma unroll
        for (int q = 0; q < 4; q++) u[q] = __ldg(xwv + (size_t)s[q] * 16);
#pragma unroll
        for (int q = 0; q < 4; q++) acc_u4(u[q], a);
        e += 4;
    }
    if (e + 2 <= end) {
        int s0 = __ldg(csr + e), s1 = __ldg(csr + e + 1);
        uint4 u0 = __ldg(xwv + (size_t)s0 * 16);
        uint4 u1 = __ldg(xwv + (size_t)s1 * 16);
        acc_u4(u0, a);
        acc_u4(u1, a);
        e += 2;
    }
    if (e < end) {
        int s0 = __ldg(csr + e);
        acc_u4(__ldg(xwv + (size_t)s0 * 16), a);
    }

    uint4 uf = __ldg((const uint4*)feat16 + (size_t)row * 16 + l16);
    float f[8];
    {
        float2 p0 = __half22float2(*(const __half2*)&uf.x);
        float2 p1 = __half22float2(*(const __half2*)&uf.y);
        float2 p2 = __half22float2(*(const __half2*)&uf.z);
        float2 p3 = __half22float2(*(const __half2*)&uf.w);
        f[0] = p0.x; f[1] = p0.y; f[2] = p1.x; f[3] = p1.y;
        f[4] = p2.x; f[5] = p2.y; f[6] = p3.x; f[7] = p3.y;
    }

    float s = __ldg(rin + row);
    float4 b0 = ((const float4*)bias)[l16 * 2];
    float4 b1 = ((const float4*)bias)[l16 * 2 + 1];
    float bb[8] = {b0.x, b0.y, b0.z, b0.w, b1.x, b1.y, b1.z, b1.w};
    float h[8];
#pragma unroll
    for (int q = 0; q < 8; q++) h[q] = fmaf(a[q], s, bb[q]) + RESC * f[q];

    if (!DO_LN) {
        float* op = (float*)o + (size_t)row * DD + l16 * 8;
        *(float4*)op = make_float4(h[0], h[1], h[2], h[3]);
        *(float4*)(op + 4) = make_float4(h[4], h[5], h[6], h[7]);
        return;
    }

    float sum = 0.f;
#pragma unroll
    for (int q = 0; q < 8; q++) sum += h[q];
#pragma unroll
    for (int off = 8; off > 0; off >>= 1) sum += __shfl_xor_sync(0xFFFFFFFFu, sum, off);
    float mu = sum * (1.0f / 128.0f);

    float d[8], sq = 0.f;
#pragma unroll
    for (int q = 0; q < 8; q++) { d[q] = h[q] - mu; sq += d[q] * d[q]; }
#pragma unroll
    for (int off = 8; off > 0; off >>= 1) sq += __shfl_xor_sync(0xFFFFFFFFu, sq, off);
    float inv = rsqrtf(sq * (1.0f / 128.0f) + LNEPS);

    float ro = __ldg(rout + row);
    float4 g0 = ((const float4*)lng)[l16 * 2];
    float4 g1 = ((const float4*)lng)[l16 * 2 + 1];
    float4 lb0 = ((const float4*)lnb)[l16 * 2];
    float4 lb1 = ((const float4*)lnb)[l16 * 2 + 1];
    float gg[8] = {g0.x, g0.y, g0.z, g0.w, g1.x, g1.y, g1.z, g1.w};
    float lb[8] = {lb0.x, lb0.y, lb0.z, lb0.w, lb1.x, lb1.y, lb1.z, lb1.w};

    float r[8];
#pragma unroll
    for (int q = 0; q < 8; q++)
        r[q] = fmaxf(fmaf(d[q] * inv, gg[q], lb[q]), 0.0f) * ro;

    uint4 w;
    *(__half2*)&w.x = __floats2half2_rn(r[0], r[1]);
    *(__half2*)&w.y = __floats2half2_rn(r[2], r[3]);
    *(__half2*)&w.z = __floats2half2_rn(r[4], r[5]);
    *(__half2*)&w.w = __floats2half2_rn(r[6], r[7]);
    ((uint4*)((__half*)o + (size_t)row * DD))[l16] = w;
}

// ---------------- launch ------------------------------------------------------
extern "C" void kernel_launch(void* const* d_in, const int* in_sizes, int n_in,
                              void* d_out, int out_size)
{
    const int*   src     = (const int*)d_in[0];
    const int*   dst     = (const int*)d_in[1];
    const float* in_feat = (const float*)d_in[2];
    const float* W1      = (const float*)d_in[3];
    const float* b1      = (const float*)d_in[4];
    const float* W2      = (const float*)d_in[5];
    const float* b2      = (const float*)d_in[6];
    const float* ln1g    = (const float*)d_in[7];
    const float* ln1b    = (const float*)d_in[8];
    const float* ln2g    = (const float*)d_in[9];
    const float* ln2b    = (const float*)d_in[10];
    float* out = (float*)d_out;

    int E = in_sizes[0];
    int n = in_sizes[2] / DD;

    __half *t, *xw, *f16, *w1t, *w2t;
    float *rout, *rin;
    unsigned long long* blob;
    int *rowptr, *cursor, *csrsrc;
    cudaGetSymbolAddress((void**)&t,      g_t);
    cudaGetSymbolAddress((void**)&xw,     g_xw);
    cudaGetSymbolAddress((void**)&f16,    g_f16);
    cudaGetSymbolAddress((void**)&w1t,    g_w1t);
    cudaGetSymbolAddress((void**)&w2t,    g_w2t);
    cudaGetSymbolAddress((void**)&rout,   g_rout);
    cudaGetSymbolAddress((void**)&rin,    g_rin);
    cudaGetSymbolAddress((void**)&blob,   g_blob);
    cudaGetSymbolAddress((void**)&rowptr, g_rowptr);
    cudaGetSymbolAddress((void**)&cursor, g_cursor);
    cudaGetSymbolAddress((void**)&csrsrc, g_csrsrc);
    int* degout = (int*)blob;
    int* degin  = degout + NMAX;
    unsigned long long* state = blob + NMAX;

    const int TB = 256;
    int gridE    = (E + TB - 1) / TB;
    int gridF    = (n * 16 + TB - 1) / TB;
    int gridRow  = (n + 15) / 16;
    int gridGemm = (n + 63) / 64;
    int gridScan = (n + 1023) / 1024;

    cudaMemsetAsync(blob, 0, (NMAX + 128) * sizeof(unsigned long long));
    prep_kernel<<<gridE + 128 + gridF, TB>>>(src, dst, degout, degin, W1, W2,
                                             w1t, w2t, in_feat, f16, E, n, gridE);
    scan_lookback_kernel<<<gridScan, 256>>>(degin, degout, state, rowptr, cursor,
                                            rout, rin, n, E);
    csr_fill_kernel<<<gridE, TB>>>(src, dst, cursor, csrsrc, E);

    // conv1
    gemm_f16_kernel<float><<<gridGemm, TB>>>(in_feat, w1t, rout, xw, n);
    agg_kernel<true, __half><<<gridRow, TB>>>(rowptr, csrsrc, xw, rin, b1, f16,
                                              ln1g, ln1b, rout, t, n);

    // conv2
    gemm_f16_kernel<__half><<<gridGemm, TB>>>(t, w2t, nullptr, xw, n);
    agg_kernel<true, __half><<<gridRow, TB>>>(rowptr, csrsrc, xw, rin, b2, f16,
                                              ln2g, ln2b, rout, t, n);

    // conv3
    gemm_f16_kernel<__half><<<gridGemm, TB>>>(t, w2t, nullptr, xw, n);
    agg_kernel<false, float><<<gridRow, TB>>>(rowptr, csrsrc, xw, rin, b2, f16,
                                              nullptr, nullptr, nullptr, out, n);
}

// round 12
// speedup vs baseline: 1.2731x; 1.0087x over previous
#include <cuda_runtime.h>
#include <cuda_fp16.h>
#include <cstdint>

#define DD 128
#define NMAX 100000
#define EMAX 1600000
#define RESC 0.2f
#define LNEPS 1e-5f

// ---------------- scratch (static device globals; no allocs allowed) --------
__device__ __half g_t[NMAX * DD];      // GEMM input (LN'd features), fp16
__device__ __half g_xw[NMAX * DD];     // GEMM output (pre-aggregation), fp16
__device__ __half g_f16[NMAX * DD];    // in_feat converted to fp16 (residual)
__device__ __half g_w1t[DD * DD];      // W1^T fp16  [n][k]
__device__ __half g_w2t[DD * DD];      // W2^T fp16  [n][k]
__device__ float  g_rout[NMAX];
__device__ float  g_rin[NMAX];
__device__ unsigned long long g_blob[NMAX + 128];  // deg ints + scan states
__device__ int    g_rowptr[NMAX + 1];
__device__ int    g_cursor[NMAX];
__device__ int    g_csrsrc[EMAX];

// ---------------- fused prep: degree + weight transpose + feat->fp16 --------
__global__ void prep_kernel(const int* __restrict__ src, const int* __restrict__ dst,
                            int* __restrict__ dout, int* __restrict__ din,
                            const float* __restrict__ W1, const float* __restrict__ W2,
                            __half* __restrict__ W1t, __half* __restrict__ W2t,
                            const float* __restrict__ feat, __half* __restrict__ feat16,
                            int e, int n, int gridE) {
    int b = blockIdx.x;
    if (b < gridE) {
        int i = b * 256 + threadIdx.x;
        if (i < e) {
            atomicAdd(dout + src[i], 1);
            atomicAdd(din + dst[i], 1);
        }
    } else if (b < gridE + 128) {
        int idx = (b - gridE) * 256 + threadIdx.x;
        int which = idx >> 14;
        int i = idx & 16383;
        int nrow = i >> 7;
        int k = i & 127;
        const float* W = which ? W2 : W1;
        __half* Wt = which ? W2t : W1t;
        Wt[nrow * DD + k] = __float2half_rn(__ldg(W + k * DD + nrow));
    } else {
        int i = (b - gridE - 128) * 256 + threadIdx.x;
        if (i < n * 16) {
            const float4* fp = (const float4*)feat + (size_t)i * 2;
            float4 f0 = __ldg(fp);
            float4 f1 = __ldg(fp + 1);
            uint4 u;
            *(__half2*)&u.x = __floats2half2_rn(f0.x, f0.y);
            *(__half2*)&u.y = __floats2half2_rn(f0.z, f0.w);
            *(__half2*)&u.z = __floats2half2_rn(f1.x, f1.y);
            *(__half2*)&u.w = __floats2half2_rn(f1.z, f1.w);
            ((uint4*)feat16)[i] = u;
        }
    }
}

// ---------------- single-pass decoupled-lookback scan ------------------------
__global__ __launch_bounds__(256) void scan_lookback_kernel(
    const int* __restrict__ degin, const int* __restrict__ degout,
    unsigned long long* __restrict__ state,
    int* __restrict__ rowptr, int* __restrict__ cursor,
    float* __restrict__ rout, float* __restrict__ rin,
    int n, int e)
{
    __shared__ int wsum[8];
    __shared__ int sExcl;
    int b = blockIdx.x;
    int t = threadIdx.x;
    int lane = t & 31, wid = t >> 5;
    int base = b * 1024 + t * 4;

    int v0 = (base + 0 < n) ? degin[base + 0] : 0;
    int v1 = (base + 1 < n) ? degin[base + 1] : 0;
    int v2 = (base + 2 < n) ? degin[base + 2] : 0;
    int v3 = (base + 3 < n) ? degin[base + 3] : 0;
    int tsum = v0 + v1 + v2 + v3;

    int x = tsum;
#pragma unroll
    for (int o = 1; o < 32; o <<= 1) {
        int y = __shfl_up_sync(0xFFFFFFFFu, x, o);
        if (lane >= o) x += y;
    }
    if (lane == 31) wsum[wid] = x;
    __syncthreads();

    if (wid == 0) {
        int w = (lane < 8) ? wsum[lane] : 0;
        int orig = w;
#pragma unroll
        for (int o = 1; o < 8; o <<= 1) {
            int y = __shfl_up_sync(0xFFFFFFFFu, w, o);
            if (lane >= o) w += y;
        }
        if (lane < 8) wsum[lane] = w - orig;
        int total = __shfl_sync(0xFFFFFFFFu, w, 7);

        if (lane == 0) {
            unsigned long long pub =
                ((unsigned long long)(b == 0 ? 2u : 1u) << 32) | (unsigned)total;
            atomicExch(&state[b], pub);
        }

        int excl = 0;
        if (b > 0) {
            int p = b - 1;
            while (true) {
                int idx = p - lane;
                unsigned long long v;
                if (idx >= 0) {
                    do { v = atomicAdd(&state[idx], 0ULL); } while ((v >> 32) == 0);
                } else {
                    v = (2ULL << 32);
                }
                unsigned flag = (unsigned)(v >> 32);
                int val = (int)(v & 0xFFFFFFFFu);
                unsigned pmask = __ballot_sync(0xFFFFFFFFu, flag == 2u);
                int c;
                if (pmask) {
                    int L = __ffs(pmask) - 1;
                    c = (lane <= L) ? val : 0;
                } else {
                    c = val;
                }
#pragma unroll
                for (int o = 16; o > 0; o >>= 1) c += __shfl_xor_sync(0xFFFFFFFFu, c, o);
                excl += c;
                if (pmask) break;
                p -= 32;
            }
            if (lane == 0)
                atomicExch(&state[b], (2ULL << 32) | (unsigned)(excl + total));
        }
        if (lane == 0) sExcl = excl;
    }
    __syncthreads();

    int texcl = wsum[wid] + x - tsum + sExcl;
    int run = texcl;
    int dv[4] = {v0, v1, v2, v3};
#pragma unroll
    for (int i = 0; i < 4; i++) {
        int idx = base + i;
        if (idx < n) {
            rowptr[idx] = run;
            cursor[idx] = run;
            rout[idx] = rsqrtf((float)max(degout[idx], 1));
            rin[idx]  = rsqrtf((float)max(dv[i], 1));
        }
        run += dv[i];
    }
    if (b == 0 && t == 0) rowptr[n] = e;
}

__global__ void csr_fill_kernel(const int* __restrict__ src, const int* __restrict__ dst,
                                int* __restrict__ cursor, int* __restrict__ csr, int e) {
    int i = blockIdx.x * blockDim.x + threadIdx.x;
    if (i < e) {
        int p = atomicAdd(cursor + dst[i], 1);
        csr[p] = src[i];
    }
}

// ---------------- FP16 tensor-core GEMM v4: R10 footprint + ldmatrix ---------
// 64x128 tile / 256 threads (8 warps: wm=wrp&1 rows, wn=wrp>>1 cols).
// W (128x128) resident (stride 136 halves), A double-buffered (stride 24 halves).
// Total static smem = 40,960 B (proven-fitting R10 footprint).
#define SWH 136   // W row stride in halves (272 B, 16B-aligned, LDSM conflict-free)
#define SAH2 24   // A stage row stride in halves (48 B, LDSM conflict-free)

__device__ __forceinline__ uint32_t smem_u32(const void* p) {
    return (uint32_t)__cvta_generic_to_shared(p);
}

__device__ __forceinline__ uint2 lda4(const __half* p, float sc) {
    (void)sc;
    return *(const uint2*)p;
}
__device__ __forceinline__ uint2 lda4(const float* p, float sc) {
    float4 f = *(const float4*)p;
    uint2 u;
    *(__half2*)&u.x = __floats2half2_rn(f.x * sc, f.y * sc);
    *(__half2*)&u.y = __floats2half2_rn(f.z * sc, f.w * sc);
    return u;
}

template <typename AT>
__global__ __launch_bounds__(256) void gemm_f16_kernel(
    const AT* __restrict__ A, const __half* __restrict__ Wt,
    const float* __restrict__ rs, __half* __restrict__ C, int n)
{
    __shared__ __half sW[128 * SWH];     // 34816 B
    __shared__ __half sA[2][64 * SAH2];  // 6144 B

    int tid = threadIdx.x;
    int lane = tid & 31;
    int wrp = tid >> 5;
    int wm = wrp & 1;        // rows wm*32
    int wn = wrp >> 1;       // cols wn*32
    int tig = lane & 3;
    int gid = lane >> 2;
    int row0 = blockIdx.x * 64;

    // ---- load full W (2048 uint4, 8/thread)
#pragma unroll
    for (int q = 0; q < 8; q++) {
        int idx = q * 256 + tid;
        int wr = idx >> 4;
        int kb = idx & 15;
        *(uint4*)&sW[wr * SWH + kb * 8] = *(const uint4*)(Wt + wr * DD + kb * 8);
    }

    // ---- A staging: thread -> (arow = tid>>2, ak = (tid&3)*4 halves)
    int arow = tid >> 2;
    int ak = (tid & 3) << 2;
    int grow = row0 + arow;
    bool rok = grow < n;
    float sc = 1.0f;
    if (rs != nullptr && rok) sc = __ldg(rs + grow);
    const AT* Ap = A + (size_t)grow * DD + ak;

    uint2 av = make_uint2(0, 0);
    if (rok) av = lda4(Ap, sc);
    *(uint2*)&sA[0][arow * SAH2 + ak] = av;
    __syncthreads();

    float acc[2][4][4];
#pragma unroll
    for (int i = 0; i < 2; i++)
#pragma unroll
        for (int j = 0; j < 4; j++)
#pragma unroll
            for (int k = 0; k < 4; k++) acc[i][j][k] = 0.0f;

    // ---- ldmatrix base addresses
    // A x4: matrices (m0..m3) = (rows+0,k0) (rows+8,k0) (rows+0,k8) (rows+8,k8)
    int quad = lane >> 3, wi = lane & 7;
    uint32_t aAddr[2][2];  // [buffer][mt]
#pragma unroll
    for (int buf = 0; buf < 2; buf++)
#pragma unroll
        for (int mt = 0; mt < 2; mt++) {
            int ar = wm * 32 + mt * 16 + wi + (quad & 1) * 8;
            aAddr[buf][mt] = smem_u32(&sA[buf][ar * SAH2 + (quad >> 1) * 8]);
        }
    // B x2: lanes 0-7 -> k-lo half (sel 0), lanes 8-15 -> k-hi (sel 1)
    int wi2 = lane & 7, sel = (lane >> 3) & 1;
    uint32_t bAddr[4];
#pragma unroll
    for (int nt = 0; nt < 4; nt++) {
        int br = wn * 32 + nt * 8 + wi2;
        bAddr[nt] = smem_u32(&sW[br * SWH + sel * 8]);
    }

    // ---- mainloop: 8 K-stages
#pragma unroll
    for (int s = 0; s < 8; s++) {
        int cur = s & 1;
        if (s < 7) {
            av = make_uint2(0, 0);
            if (rok) av = lda4(Ap + (s + 1) * 16, sc);
        }

        uint32_t af[2][4];
#pragma unroll
        for (int mt = 0; mt < 2; mt++) {
            asm volatile(
                "ldmatrix.sync.aligned.m8n8.x4.shared.b16 {%0,%1,%2,%3}, [%4];"
                : "=r"(af[mt][0]), "=r"(af[mt][1]), "=r"(af[mt][2]), "=r"(af[mt][3])
                : "r"(aAddr[cur][mt]));
        }
        uint32_t bf[4][2];
        uint32_t boff = (uint32_t)s * 32;  // 16 halves per stage
#pragma unroll
        for (int nt = 0; nt < 4; nt++) {
            asm volatile(
                "ldmatrix.sync.aligned.m8n8.x2.shared.b16 {%0,%1}, [%2];"
                : "=r"(bf[nt][0]), "=r"(bf[nt][1])
                : "r"(bAddr[nt] + boff));
        }
#pragma unroll
        for (int nt = 0; nt < 4; nt++) {
#pragma unroll
            for (int mt = 0; mt < 2; mt++) {
                asm volatile(
                    "mma.sync.aligned.m16n8k16.row.col.f32.f16.f16.f32 "
                    "{%0,%1,%2,%3}, {%4,%5,%6,%7}, {%8,%9}, {%0,%1,%2,%3};"
                    : "+f"(acc[mt][nt][0]), "+f"(acc[mt][nt][1]),
                      "+f"(acc[mt][nt][2]), "+f"(acc[mt][nt][3])
                    : "r"(af[mt][0]), "r"(af[mt][1]), "r"(af[mt][2]), "r"(af[mt][3]),
                      "r"(bf[nt][0]), "r"(bf[nt][1]));
            }
        }

        if (s < 7) {
            int nb = cur ^ 1;
            *(uint2*)&sA[nb][arow * SAH2 + ak] = av;
            __syncthreads();
        }
    }

    // ---- writeout
#pragma unroll
    for (int mt = 0; mt < 2; mt++) {
        int r0 = row0 + wm * 32 + mt * 16 + gid;
        int r1 = r0 + 8;
#pragma unroll
        for (int nt = 0; nt < 4; nt++) {
            int col = wn * 32 + nt * 8 + tig * 2;
            if (r0 < n)
                *(__half2*)(C + (size_t)r0 * DD + col) =
                    __floats2half2_rn(acc[mt][nt][0], acc[mt][nt][1]);
            if (r1 < n)
                *(__half2*)(C + (size_t)r1 * DD + col) =
                    __floats2half2_rn(acc[mt][nt][2], acc[mt][nt][3]);
        }
    }
}

// ---------------- fused CSR aggregate: half-warp per row, uint4 loads --------
__device__ __forceinline__ void acc_u4(uint4 u, float* a) {
    float2 p0 = __half22float2(*(const __half2*)&u.x);
    float2 p1 = __half22float2(*(const __half2*)&u.y);
    float2 p2 = __half22float2(*(const __half2*)&u.z);
    float2 p3 = __half22float2(*(const __half2*)&u.w);
    a[0] += p0.x; a[1] += p0.y; a[2] += p1.x; a[3] += p1.y;
    a[4] += p2.x; a[5] += p2.y; a[6] += p3.x; a[7] += p3.y;
}

template <bool DO_LN, typename OT>
__global__ void agg_kernel(const int* __restrict__ rowptr, const int* __restrict__ csr,
                           const __half* __restrict__ xw, const float* __restrict__ rin,
                           const float* __restrict__ bias, const __half* __restrict__ feat16,
                           const float* __restrict__ lng, const float* __restrict__ lnb,
                           const float* __restrict__ rout, OT* __restrict__ o, int n)
{
    int row = blockIdx.x * 16 + (threadIdx.x >> 4);
    if (row >= n) return;
    int l16 = threadIdx.x & 15;

    int beg = __ldg(rowptr + row);
    int end = __ldg(rowptr + row + 1);

    const uint4* xwv = (const uint4*)xw + l16;
    float a[8] = {0.f, 0.f, 0.f, 0.f, 0.f, 0.f, 0.f, 0.f};

    int e = beg;
    for (; e + 8 <= end; e += 8) {
        int s[8];
#pragma unroll
        for (int q = 0; q < 8; q++) s[q] = __ldg(csr + e + q);
        uint4 u[8];
#pragma unroll
        for (int q = 0; q < 8; q++) u[q] = __ldg(xwv + (size_t)s[q] * 16);
#pragma unroll
        for (int q = 0; q < 8; q++) acc_u4(u[q], a);
    }
    if (e + 4 <= end) {
        int s[4];
#pragma unroll
        for (int q = 0; q < 4; q++) s[q] = __ldg(csr + e + q);
        uint4 u[4];
#pragma unroll
        for (int q = 0; q < 4; q++) u[q] = __ldg(xwv + (size_t)s[q] * 16);
#pragma unroll
        for (int q = 0; q < 4; q++) acc_u4(u[q], a);
        e += 4;
    }
    if (e + 2 <= end) {
        int s0 = __ldg(csr + e), s1 = __ldg(csr + e + 1);
        uint4 u0 = __ldg(xwv + (size_t)s0 * 16);
        uint4 u1 = __ldg(xwv + (size_t)s1 * 16);
        acc_u4(u0, a);
        acc_u4(u1, a);
        e += 2;
    }
    if (e < end) {
        int s0 = __ldg(csr + e);
        acc_u4(__ldg(xwv + (size_t)s0 * 16), a);
    }

    uint4 uf = __ldg((const uint4*)feat16 + (size_t)row * 16 + l16);
    float f[8];
    {
        float2 p0 = __half22float2(*(const __half2*)&uf.x);
        float2 p1 = __half22float2(*(const __half2*)&uf.y);
        float2 p2 = __half22float2(*(const __half2*)&uf.z);
        float2 p3 = __half22float2(*(const __half2*)&uf.w);
        f[0] = p0.x; f[1] = p0.y; f[2] = p1.x; f[3] = p1.y;
        f[4] = p2.x; f[5] = p2.y; f[6] = p3.x; f[7] = p3.y;
    }

    float s = __ldg(rin + row);
    float4 b0 = ((const float4*)bias)[l16 * 2];
    float4 b1 = ((const float4*)bias)[l16 * 2 + 1];
    float bb[8] = {b0.x, b0.y, b0.z, b0.w, b1.x, b1.y, b1.z, b1.w};
    float h[8];
#pragma unroll
    for (int q = 0; q < 8; q++) h[q] = fmaf(a[q], s, bb[q]) + RESC * f[q];

    if (!DO_LN) {
        float* op = (float*)o + (size_t)row * DD + l16 * 8;
        *(float4*)op = make_float4(h[0], h[1], h[2], h[3]);
        *(float4*)(op + 4) = make_float4(h[4], h[5], h[6], h[7]);
        return;
    }

    float sum = 0.f;
#pragma unroll
    for (int q = 0; q < 8; q++) sum += h[q];
#pragma unroll
    for (int off = 8; off > 0; off >>= 1) sum += __shfl_xor_sync(0xFFFFFFFFu, sum, off);
    float mu = sum * (1.0f / 128.0f);

    float d[8], sq = 0.f;
#pragma unroll
    for (int q = 0; q < 8; q++) { d[q] = h[q] - mu; sq += d[q] * d[q]; }
#pragma unroll
    for (int off = 8; off > 0; off >>= 1) sq += __shfl_xor_sync(0xFFFFFFFFu, sq, off);
    float inv = rsqrtf(sq * (1.0f / 128.0f) + LNEPS);

    float ro = __ldg(rout + row);
    float4 g0 = ((const float4*)lng)[l16 * 2];
    float4 g1 = ((const float4*)lng)[l16 * 2 + 1];
    float4 lb0 = ((const float4*)lnb)[l16 * 2];
    float4 lb1 = ((const float4*)lnb)[l16 * 2 + 1];
    float gg[8] = {g0.x, g0.y, g0.z, g0.w, g1.x, g1.y, g1.z, g1.w};
    float lb[8] = {lb0.x, lb0.y, lb0.z, lb0.w, lb1.x, lb1.y, lb1.z, lb1.w};

    float r[8];
#pragma unroll
    for (int q = 0; q < 8; q++)
        r[q] = fmaxf(fmaf(d[q] * inv, gg[q], lb[q]), 0.0f) * ro;

    uint4 w;
    *(__half2*)&w.x = __floats2half2_rn(r[0], r[1]);
    *(__half2*)&w.y = __floats2half2_rn(r[2], r[3]);
    *(__half2*)&w.z = __floats2half2_rn(r[4], r[5]);
    *(__half2*)&w.w = __floats2half2_rn(r[6], r[7]);
    ((uint4*)((__half*)o + (size_t)row * DD))[l16] = w;
}

// ---------------- launch ------------------------------------------------------
extern "C" void kernel_launch(void* const* d_in, const int* in_sizes, int n_in,
                              void* d_out, int out_size)
{
    const int*   src     = (const int*)d_in[0];
    const int*   dst     = (const int*)d_in[1];
    const float* in_feat = (const float*)d_in[2];
    const float* W1      = (const float*)d_in[3];
    const float* b1      = (const float*)d_in[4];
    const float* W2      = (const float*)d_in[5];
    const float* b2      = (const float*)d_in[6];
    const float* ln1g    = (const float*)d_in[7];
    const float* ln1b    = (const float*)d_in[8];
    const float* ln2g    = (const float*)d_in[9];
    const float* ln2b    = (const float*)d_in[10];
    float* out = (float*)d_out;

    int E = in_sizes[0];
    int n = in_sizes[2] / DD;

    __half *t, *xw, *f16, *w1t, *w2t;
    float *rout, *rin;
    unsigned long long* blob;
    int *rowptr, *cursor, *csrsrc;
    cudaGetSymbolAddress((void**)&t,      g_t);
    cudaGetSymbolAddress((void**)&xw,     g_xw);
    cudaGetSymbolAddress((void**)&f16,    g_f16);
    cudaGetSymbolAddress((void**)&w1t,    g_w1t);
    cudaGetSymbolAddress((void**)&w2t,    g_w2t);
    cudaGetSymbolAddress((void**)&rout,   g_rout);
    cudaGetSymbolAddress((void**)&rin,    g_rin);
    cudaGetSymbolAddress((void**)&blob,   g_blob);
    cudaGetSymbolAddress((void**)&rowptr, g_rowptr);
    cudaGetSymbolAddress((void**)&cursor, g_cursor);
    cudaGetSymbolAddress((void**)&csrsrc, g_csrsrc);
    int* degout = (int*)blob;
    int* degin  = degout + NMAX;
    unsigned long long* state = blob + NMAX;

    const int TB = 256;
    int gridE    = (E + TB - 1) / TB;
    int gridF    = (n * 16 + TB - 1) / TB;
    int gridRow  = (n + 15) / 16;
    int gridGemm = (n + 63) / 64;
    int gridScan = (n + 1023) / 1024;

    cudaMemsetAsync(blob, 0, (NMAX + 128) * sizeof(unsigned long long));
    prep_kernel<<<gridE + 128 + gridF, TB>>>(src, dst, degout, degin, W1, W2,
                                             w1t, w2t, in_feat, f16, E, n, gridE);
    scan_lookback_kernel<<<gridScan, 256>>>(degin, degout, state, rowptr, cursor,
                                            rout, rin, n, E);
    csr_fill_kernel<<<gridE, TB>>>(src, dst, cursor, csrsrc, E);

    // conv1
    gemm_f16_kernel<float><<<gridGemm, TB>>>(in_feat, w1t, rout, xw, n);
    agg_kernel<true, __half><<<gridRow, TB>>>(rowptr, csrsrc, xw, rin, b1, f16,
                                              ln1g, ln1b, rout, t, n);

    // conv2
    gemm_f16_kernel<__half><<<gridGemm, TB>>>(t, w2t, nullptr, xw, n);
    agg_kernel<true, __half><<<gridRow, TB>>>(rowptr, csrsrc, xw, rin, b2, f16,
                                              ln2g, ln2b, rout, t, n);

    // conv3
    gemm_f16_kernel<__half><<<gridGemm, TB>>>(t, w2t, nullptr, xw, n);
    agg_kernel<false, float><<<gridRow, TB>>>(rowptr, csrsrc, xw, rin, b2, f16,
                                              nullptr, nullptr, nullptr, out, n);
}

// round 13
// speedup vs baseline: 1.2975x; 1.0192x over previous
#include <cuda_runtime.h>
#include <cuda_fp16.h>
#include <cstdint>

#define DD 128
#define NMAX 100000
#define EMAX 1600000
#define RESC 0.2f
#define LNEPS 1e-5f

// ---------------- scratch (static device globals; no allocs allowed) --------
__device__ __half g_t[NMAX * DD];      // GEMM input (LN'd features), fp16
__device__ __half g_xw[NMAX * DD];     // GEMM output (pre-aggregation), fp16
__device__ __half g_f16[NMAX * DD];    // in_feat converted to fp16 (residual)
__device__ __half g_w1t[DD * DD];      // W1^T fp16  [n][k]
__device__ __half g_w2t[DD * DD];      // W2^T fp16  [n][k]
__device__ float  g_rout[NMAX];
__device__ float  g_rin[NMAX];
__device__ unsigned long long g_blob[NMAX + 128];  // deg ints + scan states
__device__ int    g_rowptr[NMAX + 1];
__device__ int    g_cursor[NMAX];
__device__ int    g_csrsrc[EMAX];

// ---------------- fused prep: degree + weight transpose + feat->fp16 --------
__global__ void prep_kernel(const int* __restrict__ src, const int* __restrict__ dst,
                            int* __restrict__ dout, int* __restrict__ din,
                            const float* __restrict__ W1, const float* __restrict__ W2,
                            __half* __restrict__ W1t, __half* __restrict__ W2t,
                            const float* __restrict__ feat, __half* __restrict__ feat16,
                            int e, int n, int gridE) {
    int b = blockIdx.x;
    if (b < gridE) {
        int i = b * 256 + threadIdx.x;
        if (i < e) {
            atomicAdd(dout + src[i], 1);
            atomicAdd(din + dst[i], 1);
        }
    } else if (b < gridE + 128) {
        int idx = (b - gridE) * 256 + threadIdx.x;
        int which = idx >> 14;
        int i = idx & 16383;
        int nrow = i >> 7;
        int k = i & 127;
        const float* W = which ? W2 : W1;
        __half* Wt = which ? W2t : W1t;
        Wt[nrow * DD + k] = __float2half_rn(__ldg(W + k * DD + nrow));
    } else {
        int i = (b - gridE - 128) * 256 + threadIdx.x;
        if (i < n * 16) {
            const float4* fp = (const float4*)feat + (size_t)i * 2;
            float4 f0 = __ldg(fp);
            float4 f1 = __ldg(fp + 1);
            uint4 u;
            *(__half2*)&u.x = __floats2half2_rn(f0.x, f0.y);
            *(__half2*)&u.y = __floats2half2_rn(f0.z, f0.w);
            *(__half2*)&u.z = __floats2half2_rn(f1.x, f1.y);
            *(__half2*)&u.w = __floats2half2_rn(f1.z, f1.w);
            ((uint4*)feat16)[i] = u;
        }
    }
}

// ---------------- single-pass decoupled-lookback scan ------------------------
__global__ __launch_bounds__(256) void scan_lookback_kernel(
    const int* __restrict__ degin, const int* __restrict__ degout,
    unsigned long long* __restrict__ state,
    int* __restrict__ rowptr, int* __restrict__ cursor,
    float* __restrict__ rout, float* __restrict__ rin,
    int n, int e)
{
    __shared__ int wsum[8];
    __shared__ int sExcl;
    int b = blockIdx.x;
    int t = threadIdx.x;
    int lane = t & 31, wid = t >> 5;
    int base = b * 1024 + t * 4;

    int v0 = (base + 0 < n) ? degin[base + 0] : 0;
    int v1 = (base + 1 < n) ? degin[base + 1] : 0;
    int v2 = (base + 2 < n) ? degin[base + 2] : 0;
    int v3 = (base + 3 < n) ? degin[base + 3] : 0;
    int tsum = v0 + v1 + v2 + v3;

    int x = tsum;
#pragma unroll
    for (int o = 1; o < 32; o <<= 1) {
        int y = __shfl_up_sync(0xFFFFFFFFu, x, o);
        if (lane >= o) x += y;
    }
    if (lane == 31) wsum[wid] = x;
    __syncthreads();

    if (wid == 0) {
        int w = (lane < 8) ? wsum[lane] : 0;
        int orig = w;
#pragma unroll
        for (int o = 1; o < 8; o <<= 1) {
            int y = __shfl_up_sync(0xFFFFFFFFu, w, o);
            if (lane >= o) w += y;
        }
        if (lane < 8) wsum[lane] = w - orig;
        int total = __shfl_sync(0xFFFFFFFFu, w, 7);

        if (lane == 0) {
            unsigned long long pub =
                ((unsigned long long)(b == 0 ? 2u : 1u) << 32) | (unsigned)total;
            atomicExch(&state[b], pub);
        }

        int excl = 0;
        if (b > 0) {
            int p = b - 1;
            while (true) {
                int idx = p - lane;
                unsigned long long v;
                if (idx >= 0) {
                    do { v = atomicAdd(&state[idx], 0ULL); } while ((v >> 32) == 0);
                } else {
                    v = (2ULL << 32);
                }
                unsigned flag = (unsigned)(v >> 32);
                int val = (int)(v & 0xFFFFFFFFu);
                unsigned pmask = __ballot_sync(0xFFFFFFFFu, flag == 2u);
                int c;
                if (pmask) {
                    int L = __ffs(pmask) - 1;
                    c = (lane <= L) ? val : 0;
                } else {
                    c = val;
                }
#pragma unroll
                for (int o = 16; o > 0; o >>= 1) c += __shfl_xor_sync(0xFFFFFFFFu, c, o);
                excl += c;
                if (pmask) break;
                p -= 32;
            }
            if (lane == 0)
                atomicExch(&state[b], (2ULL << 32) | (unsigned)(excl + total));
        }
        if (lane == 0) sExcl = excl;
    }
    __syncthreads();

    int texcl = wsum[wid] + x - tsum + sExcl;
    int run = texcl;
    int dv[4] = {v0, v1, v2, v3};
#pragma unroll
    for (int i = 0; i < 4; i++) {
        int idx = base + i;
        if (idx < n) {
            rowptr[idx] = run;
            cursor[idx] = run;
            rout[idx] = rsqrtf((float)max(degout[idx], 1));
            rin[idx]  = rsqrtf((float)max(dv[i], 1));
        }
        run += dv[i];
    }
    if (b == 0 && t == 0) rowptr[n] = e;
}

__global__ void csr_fill_kernel(const int* __restrict__ src, const int* __restrict__ dst,
                                int* __restrict__ cursor, int* __restrict__ csr, int e) {
    int i = blockIdx.x * blockDim.x + threadIdx.x;
    if (i < e) {
        int p = atomicAdd(cursor + dst[i], 1);
        csr[p] = src[i];
    }
}

// ---------------- FP16 tensor-core GEMM v5: persistent W + grid-stride tiles -
// 64x128 tile / 256 threads (8 warps: wm=wrp&1 rows, wn=wrp>>1 cols).
// W loaded ONCE per block (stride 136 halves), then grid-stride loop over
// 64-row A tiles (A double-buffered, stride 24 halves). 41 KB static smem.
#define SWH 136
#define SAH2 24
#define GEMM_BLOCKS 444

__device__ __forceinline__ uint32_t smem_u32(const void* p) {
    return (uint32_t)__cvta_generic_to_shared(p);
}

__device__ __forceinline__ uint2 lda4(const __half* p, float sc) {
    (void)sc;
    return *(const uint2*)p;
}
__device__ __forceinline__ uint2 lda4(const float* p, float sc) {
    float4 f = *(const float4*)p;
    uint2 u;
    *(__half2*)&u.x = __floats2half2_rn(f.x * sc, f.y * sc);
    *(__half2*)&u.y = __floats2half2_rn(f.z * sc, f.w * sc);
    return u;
}

template <typename AT>
__global__ __launch_bounds__(256) void gemm_f16_kernel(
    const AT* __restrict__ A, const __half* __restrict__ Wt,
    const float* __restrict__ rs, __half* __restrict__ C, int n)
{
    __shared__ __half sW[128 * SWH];     // 34816 B
    __shared__ __half sA[2][64 * SAH2];  // 6144 B

    int tid = threadIdx.x;
    int lane = tid & 31;
    int wrp = tid >> 5;
    int wm = wrp & 1;
    int wn = wrp >> 1;
    int tig = lane & 3;
    int gid = lane >> 2;

    // ---- load full W once (2048 uint4, 8/thread)
#pragma unroll
    for (int q = 0; q < 8; q++) {
        int idx = q * 256 + tid;
        int wr = idx >> 4;
        int kb = idx & 15;
        *(uint4*)&sW[wr * SWH + kb * 8] = *(const uint4*)(Wt + wr * DD + kb * 8);
    }

    // ---- ldmatrix base addresses (fixed across tiles)
    int quad = lane >> 3, wi = lane & 7;
    uint32_t aAddr[2][2];
#pragma unroll
    for (int buf = 0; buf < 2; buf++)
#pragma unroll
        for (int mt = 0; mt < 2; mt++) {
            int ar = wm * 32 + mt * 16 + wi + (quad & 1) * 8;
            aAddr[buf][mt] = smem_u32(&sA[buf][ar * SAH2 + (quad >> 1) * 8]);
        }
    int wi2 = lane & 7, sel = (lane >> 3) & 1;
    uint32_t bAddr[4];
#pragma unroll
    for (int nt = 0; nt < 4; nt++) {
        int br = wn * 32 + nt * 8 + wi2;
        bAddr[nt] = smem_u32(&sW[br * SWH + sel * 8]);
    }

    int arow = tid >> 2;
    int ak = (tid & 3) << 2;
    int nTiles = (n + 63) >> 6;

    for (int tile = blockIdx.x; tile < nTiles; tile += GEMM_BLOCKS) {
        int row0 = tile * 64;
        int grow = row0 + arow;
        bool rok = grow < n;
        float sc = 1.0f;
        if (rs != nullptr && rok) sc = __ldg(rs + grow);
        const AT* Ap = A + (size_t)grow * DD + ak;

        uint2 av = make_uint2(0, 0);
        if (rok) av = lda4(Ap, sc);
        *(uint2*)&sA[0][arow * SAH2 + ak] = av;
        __syncthreads();

        float acc[2][4][4];
#pragma unroll
        for (int i = 0; i < 2; i++)
#pragma unroll
            for (int j = 0; j < 4; j++)
#pragma unroll
                for (int k = 0; k < 4; k++) acc[i][j][k] = 0.0f;

#pragma unroll
        for (int s = 0; s < 8; s++) {
            int cur = s & 1;
            if (s < 7) {
                av = make_uint2(0, 0);
                if (rok) av = lda4(Ap + (s + 1) * 16, sc);
            }

            uint32_t af[2][4];
#pragma unroll
            for (int mt = 0; mt < 2; mt++) {
                asm volatile(
                    "ldmatrix.sync.aligned.m8n8.x4.shared.b16 {%0,%1,%2,%3}, [%4];"
                    : "=r"(af[mt][0]), "=r"(af[mt][1]), "=r"(af[mt][2]), "=r"(af[mt][3])
                    : "r"(aAddr[cur][mt]));
            }
            uint32_t bf[4][2];
            uint32_t boff = (uint32_t)s * 32;
#pragma unroll
            for (int nt = 0; nt < 4; nt++) {
                asm volatile(
                    "ldmatrix.sync.aligned.m8n8.x2.shared.b16 {%0,%1}, [%2];"
                    : "=r"(bf[nt][0]), "=r"(bf[nt][1])
                    : "r"(bAddr[nt] + boff));
            }
#pragma unroll
            for (int nt = 0; nt < 4; nt++) {
#pragma unroll
                for (int mt = 0; mt < 2; mt++) {
                    asm volatile(
                        "mma.sync.aligned.m16n8k16.row.col.f32.f16.f16.f32 "
                        "{%0,%1,%2,%3}, {%4,%5,%6,%7}, {%8,%9}, {%0,%1,%2,%3};"
                        : "+f"(acc[mt][nt][0]), "+f"(acc[mt][nt][1]),
                          "+f"(acc[mt][nt][2]), "+f"(acc[mt][nt][3])
                        : "r"(af[mt][0]), "r"(af[mt][1]), "r"(af[mt][2]), "r"(af[mt][3]),
                          "r"(bf[nt][0]), "r"(bf[nt][1]));
                }
            }

            if (s < 7) {
                int nb = cur ^ 1;
                *(uint2*)&sA[nb][arow * SAH2 + ak] = av;
                __syncthreads();
            }
        }

        // writeout (registers only; stage-7 read buffer 1, next tile writes
        // buffer 0 then barriers, so cross-tile smem reuse is race-free)
#pragma unroll
        for (int mt = 0; mt < 2; mt++) {
            int r0 = row0 + wm * 32 + mt * 16 + gid;
            int r1 = r0 + 8;
#pragma unroll
            for (int nt = 0; nt < 4; nt++) {
                int col = wn * 32 + nt * 8 + tig * 2;
                if (r0 < n)
                    *(__half2*)(C + (size_t)r0 * DD + col) =
                        __floats2half2_rn(acc[mt][nt][0], acc[mt][nt][1]);
                if (r1 < n)
                    *(__half2*)(C + (size_t)r1 * DD + col) =
                        __floats2half2_rn(acc[mt][nt][2], acc[mt][nt][3]);
            }
        }
    }
}

// ---------------- fused CSR aggregate: half-warp per row, uint4 loads --------
__device__ __forceinline__ void acc_u4(uint4 u, float* a) {
    float2 p0 = __half22float2(*(const __half2*)&u.x);
    float2 p1 = __half22float2(*(const __half2*)&u.y);
    float2 p2 = __half22float2(*(const __half2*)&u.z);
    float2 p3 = __half22float2(*(const __half2*)&u.w);
    a[0] += p0.x; a[1] += p0.y; a[2] += p1.x; a[3] += p1.y;
    a[4] += p2.x; a[5] += p2.y; a[6] += p3.x; a[7] += p3.y;
}

template <bool DO_LN, typename OT>
__global__ void agg_kernel(const int* __restrict__ rowptr, const int* __restrict__ csr,
                           const __half* __restrict__ xw, const float* __restrict__ rin,
                           const float* __restrict__ bias, const __half* __restrict__ feat16,
                           const float* __restrict__ lng, const float* __restrict__ lnb,
                           const float* __restrict__ rout, OT* __restrict__ o, int n)
{
    int row = blockIdx.x * 16 + (threadIdx.x >> 4);
    if (row >= n) return;
    int l16 = threadIdx.x & 15;

    int beg = __ldg(rowptr + row);
    int end = __ldg(rowptr + row + 1);

    const uint4* xwv = (const uint4*)xw + l16;
    float a[8] = {0.f, 0.f, 0.f, 0.f, 0.f, 0.f, 0.f, 0.f};

    int e = beg;
    for (; e + 8 <= end; e += 8) {
        int s[8];
#pragma unroll
        for (int q = 0; q < 8; q++) s[q] = __ldg(csr + e + q);
        uint4 u[8];
#pragma unroll
        for (int q = 0; q < 8; q++) u[q] = __ldg(xwv + (size_t)s[q] * 16);
#pragma unroll
        for (int q = 0; q < 8; q++) acc_u4(u[q], a);
    }
    if (e + 4 <= end) {
        int s[4];
#pragma unroll
        for (int q = 0; q < 4; q++) s[q] = __ldg(csr + e + q);
        uint4 u[4];
#pragma unroll
        for (int q = 0; q < 4; q++) u[q] = __ldg(xwv + (size_t)s[q] * 16);
#pragma unroll
        for (int q = 0; q < 4; q++) acc_u4(u[q], a);
        e += 4;
    }
    if (e + 2 <= end) {
        int s0 = __ldg(csr + e), s1 = __ldg(csr + e + 1);
        uint4 u0 = __ldg(xwv + (size_t)s0 * 16);
        uint4 u1 = __ldg(xwv + (size_t)s1 * 16);
        acc_u4(u0, a);
        acc_u4(u1, a);
        e += 2;
    }
    if (e < end) {
        int s0 = __ldg(csr + e);
        acc_u4(__ldg(xwv + (size_t)s0 * 16), a);
    }

    uint4 uf = __ldg((const uint4*)feat16 + (size_t)row * 16 + l16);
    float f[8];
    {
        float2 p0 = __half22float2(*(const __half2*)&uf.x);
        float2 p1 = __half22float2(*(const __half2*)&uf.y);
        float2 p2 = __half22float2(*(const __half2*)&uf.z);
        float2 p3 = __half22float2(*(const __half2*)&uf.w);
        f[0] = p0.x; f[1] = p0.y; f[2] = p1.x; f[3] = p1.y;
        f[4] = p2.x; f[5] = p2.y; f[6] = p3.x; f[7] = p3.y;
    }

    float s = __ldg(rin + row);
    float4 b0 = ((const float4*)bias)[l16 * 2];
    float4 b1 = ((const float4*)bias)[l16 * 2 + 1];
    float bb[8] = {b0.x, b0.y, b0.z, b0.w, b1.x, b1.y, b1.z, b1.w};
    float h[8];
#pragma unroll
    for (int q = 0; q < 8; q++) h[q] = fmaf(a[q], s, bb[q]) + RESC * f[q];

    if (!DO_LN) {
        float* op = (float*)o + (size_t)row * DD + l16 * 8;
        *(float4*)op = make_float4(h[0], h[1], h[2], h[3]);
        *(float4*)(op + 4) = make_float4(h[4], h[5], h[6], h[7]);
        return;
    }

    float sum = 0.f;
#pragma unroll
    for (int q = 0; q < 8; q++) sum += h[q];
#pragma unroll
    for (int off = 8; off > 0; off >>= 1) sum += __shfl_xor_sync(0xFFFFFFFFu, sum, off);
    float mu = sum * (1.0f / 128.0f);

    float d[8], sq = 0.f;
#pragma unroll
    for (int q = 0; q < 8; q++) { d[q] = h[q] - mu; sq += d[q] * d[q]; }
#pragma unroll
    for (int off = 8; off > 0; off >>= 1) sq += __shfl_xor_sync(0xFFFFFFFFu, sq, off);
    float inv = rsqrtf(sq * (1.0f / 128.0f) + LNEPS);

    float ro = __ldg(rout + row);
    float4 g0 = ((const float4*)lng)[l16 * 2];
    float4 g1 = ((const float4*)lng)[l16 * 2 + 1];
    float4 lb0 = ((const float4*)lnb)[l16 * 2];
    float4 lb1 = ((const float4*)lnb)[l16 * 2 + 1];
    float gg[8] = {g0.x, g0.y, g0.z, g0.w, g1.x, g1.y, g1.z, g1.w};
    float lb[8] = {lb0.x, lb0.y, lb0.z, lb0.w, lb1.x, lb1.y, lb1.z, lb1.w};

    float r[8];
#pragma unroll
    for (int q = 0; q < 8; q++)
        r[q] = fmaxf(fmaf(d[q] * inv, gg[q], lb[q]), 0.0f) * ro;

    uint4 w;
    *(__half2*)&w.x = __floats2half2_rn(r[0], r[1]);
    *(__half2*)&w.y = __floats2half2_rn(r[2], r[3]);
    *(__half2*)&w.z = __floats2half2_rn(r[4], r[5]);
    *(__half2*)&w.w = __floats2half2_rn(r[6], r[7]);
    ((uint4*)((__half*)o + (size_t)row * DD))[l16] = w;
}

// ---------------- launch ------------------------------------------------------
extern "C" void kernel_launch(void* const* d_in, const int* in_sizes, int n_in,
                              void* d_out, int out_size)
{
    const int*   src     = (const int*)d_in[0];
    const int*   dst     = (const int*)d_in[1];
    const float* in_feat = (const float*)d_in[2];
    const float* W1      = (const float*)d_in[3];
    const float* b1      = (const float*)d_in[4];
    const float* W2      = (const float*)d_in[5];
    const float* b2      = (const float*)d_in[6];
    const float* ln1g    = (const float*)d_in[7];
    const float* ln1b    = (const float*)d_in[8];
    const float* ln2g    = (const float*)d_in[9];
    const float* ln2b    = (const float*)d_in[10];
    float* out = (float*)d_out;

    int E = in_sizes[0];
    int n = in_sizes[2] / DD;

    __half *t, *xw, *f16, *w1t, *w2t;
    float *rout, *rin;
    unsigned long long* blob;
    int *rowptr, *cursor, *csrsrc;
    cudaGetSymbolAddress((void**)&t,      g_t);
    cudaGetSymbolAddress((void**)&xw,     g_xw);
    cudaGetSymbolAddress((void**)&f16,    g_f16);
    cudaGetSymbolAddress((void**)&w1t,    g_w1t);
    cudaGetSymbolAddress((void**)&w2t,    g_w2t);
    cudaGetSymbolAddress((void**)&rout,   g_rout);
    cudaGetSymbolAddress((void**)&rin,    g_rin);
    cudaGetSymbolAddress((void**)&blob,   g_blob);
    cudaGetSymbolAddress((void**)&rowptr, g_rowptr);
    cudaGetSymbolAddress((void**)&cursor, g_cursor);
    cudaGetSymbolAddress((void**)&csrsrc, g_csrsrc);
    int* degout = (int*)blob;
    int* degin  = degout + NMAX;
    unsigned long long* state = blob + NMAX;

    const int TB = 256;
    int gridE    = (E + TB - 1) / TB;
    int gridF    = (n * 16 + TB - 1) / TB;
    int gridRow  = (n + 15) / 16;
    int nTiles   = (n + 63) / 64;
    int gridGemm = nTiles < GEMM_BLOCKS ? nTiles : GEMM_BLOCKS;
    int gridScan = (n + 1023) / 1024;

    cudaMemsetAsync(blob, 0, (NMAX + 128) * sizeof(unsigned long long));
    prep_kernel<<<gridE + 128 + gridF, TB>>>(src, dst, degout, degin, W1, W2,
                                             w1t, w2t, in_feat, f16, E, n, gridE);
    scan_lookback_kernel<<<gridScan, 256>>>(degin, degout, state, rowptr, cursor,
                                            rout, rin, n, E);
    csr_fill_kernel<<<gridE, TB>>>(src, dst, cursor, csrsrc, E);

    // conv1
    gemm_f16_kernel<float><<<gridGemm, TB>>>(in_feat, w1t, rout, xw, n);
    agg_kernel<true, __half><<<gridRow, TB>>>(rowptr, csrsrc, xw, rin, b1, f16,
                                              ln1g, ln1b, rout, t, n);

    // conv2
    gemm_f16_kernel<__half><<<gridGemm, TB>>>(t, w2t, nullptr, xw, n);
    agg_kernel<true, __half><<<gridRow, TB>>>(rowptr, csrsrc, xw, rin, b2, f16,
                                              ln2g, ln2b, rout, t, n);

    // conv3
    gemm_f16_kernel<__half><<<gridGemm, TB>>>(t, w2t, nullptr, xw, n);
    agg_kernel<false, float><<<gridRow, TB>>>(rowptr, csrsrc, xw, rin, b2, f16,
                                              nullptr, nullptr, nullptr, out, n);
}

// round 15
// speedup vs baseline: 1.3074x; 1.0077x over previous
#include <cuda_runtime.h>
#include <cuda_fp16.h>
#include <cstdint>

#define DD 128
#define NMAX 100000
#define EMAX 1600000
#define RESC 0.2f
#define LNEPS 1e-5f

// ---------------- scratch (static device globals; no allocs allowed) --------
__device__ __half g_t[NMAX * DD];      // GEMM input (LN'd features), fp16
__device__ __half g_xw[NMAX * DD];     // GEMM output (pre-aggregation), fp16
__device__ __half g_f16[NMAX * DD];    // in_feat converted to fp16 (residual + conv1 A)
__device__ __half g_w1t[DD * DD];      // W1^T fp16  [n][k]
__device__ __half g_w2t[DD * DD];      // W2^T fp16  [n][k]
__device__ float  g_rout[NMAX];
__device__ float  g_rin[NMAX];
__device__ unsigned long long g_blob[NMAX + 128];  // deg ints + scan states
__device__ int    g_rowptr[NMAX + 1];
__device__ int    g_cursor[NMAX];
__device__ int    g_csrsrc[EMAX];

// ---------------- fused prep: degree + weight transpose + feat->fp16 --------
__global__ void prep_kernel(const int* __restrict__ src, const int* __restrict__ dst,
                            int* __restrict__ dout, int* __restrict__ din,
                            const float* __restrict__ W1, const float* __restrict__ W2,
                            __half* __restrict__ W1t, __half* __restrict__ W2t,
                            const float* __restrict__ feat, __half* __restrict__ feat16,
                            int e, int n, int gridE) {
    int b = blockIdx.x;
    if (b < gridE) {
        int i = b * 256 + threadIdx.x;
        if (i < e) {
            atomicAdd(dout + src[i], 1);
            atomicAdd(din + dst[i], 1);
        }
    } else if (b < gridE + 128) {
        int idx = (b - gridE) * 256 + threadIdx.x;
        int which = idx >> 14;
        int i = idx & 16383;
        int nrow = i >> 7;
        int k = i & 127;
        const float* W = which ? W2 : W1;
        __half* Wt = which ? W2t : W1t;
        Wt[nrow * DD + k] = __float2half_rn(__ldg(W + k * DD + nrow));
    } else {
        int i = (b - gridE - 128) * 256 + threadIdx.x;
        if (i < n * 16) {
            const float4* fp = (const float4*)feat + (size_t)i * 2;
            float4 f0 = __ldg(fp);
            float4 f1 = __ldg(fp + 1);
            uint4 u;
            *(__half2*)&u.x = __floats2half2_rn(f0.x, f0.y);
            *(__half2*)&u.y = __floats2half2_rn(f0.z, f0.w);
            *(__half2*)&u.z = __floats2half2_rn(f1.x, f1.y);
            *(__half2*)&u.w = __floats2half2_rn(f1.z, f1.w);
            ((uint4*)feat16)[i] = u;
        }
    }
}

// ---------------- single-pass decoupled-lookback scan ------------------------
__global__ __launch_bounds__(256) void scan_lookback_kernel(
    const int* __restrict__ degin, const int* __restrict__ degout,
    unsigned long long* __restrict__ state,
    int* __restrict__ rowptr, int* __restrict__ cursor,
    float* __restrict__ rout, float* __restrict__ rin,
    int n, int e)
{
    __shared__ int wsum[8];
    __shared__ int sExcl;
    int b = blockIdx.x;
    int t = threadIdx.x;
    int lane = t & 31, wid = t >> 5;
    int base = b * 1024 + t * 4;

    int v0 = (base + 0 < n) ? degin[base + 0] : 0;
    int v1 = (base + 1 < n) ? degin[base + 1] : 0;
    int v2 = (base + 2 < n) ? degin[base + 2] : 0;
    int v3 = (base + 3 < n) ? degin[base + 3] : 0;
    int tsum = v0 + v1 + v2 + v3;

    int x = tsum;
#pragma unroll
    for (int o = 1; o < 32; o <<= 1) {
        int y = __shfl_up_sync(0xFFFFFFFFu, x, o);
        if (lane >= o) x += y;
    }
    if (lane == 31) wsum[wid] = x;
    __syncthreads();

    if (wid == 0) {
        int w = (lane < 8) ? wsum[lane] : 0;
        int orig = w;
#pragma unroll
        for (int o = 1; o < 8; o <<= 1) {
            int y = __shfl_up_sync(0xFFFFFFFFu, w, o);
            if (lane >= o) w += y;
        }
        if (lane < 8) wsum[lane] = w - orig;
        int total = __shfl_sync(0xFFFFFFFFu, w, 7);

        if (lane == 0) {
            unsigned long long pub =
                ((unsigned long long)(b == 0 ? 2u : 1u) << 32) | (unsigned)total;
            atomicExch(&state[b], pub);
        }

        int excl = 0;
        if (b > 0) {
            int p = b - 1;
            while (true) {
                int idx = p - lane;
                unsigned long long v;
                if (idx >= 0) {
                    do { v = atomicAdd(&state[idx], 0ULL); } while ((v >> 32) == 0);
                } else {
                    v = (2ULL << 32);
                }
                unsigned flag = (unsigned)(v >> 32);
                int val = (int)(v & 0xFFFFFFFFu);
                unsigned pmask = __ballot_sync(0xFFFFFFFFu, flag == 2u);
                int c;
                if (pmask) {
                    int L = __ffs(pmask) - 1;
                    c = (lane <= L) ? val : 0;
                } else {
                    c = val;
                }
#pragma unroll
                for (int o = 16; o > 0; o >>= 1) c += __shfl_xor_sync(0xFFFFFFFFu, c, o);
                excl += c;
                if (pmask) break;
                p -= 32;
            }
            if (lane == 0)
                atomicExch(&state[b], (2ULL << 32) | (unsigned)(excl + total));
        }
        if (lane == 0) sExcl = excl;
    }
    __syncthreads();

    int texcl = wsum[wid] + x - tsum + sExcl;
    int run = texcl;
    int dv[4] = {v0, v1, v2, v3};
#pragma unroll
    for (int i = 0; i < 4; i++) {
        int idx = base + i;
        if (idx < n) {
            rowptr[idx] = run;
            cursor[idx] = run;
            rout[idx] = rsqrtf((float)max(degout[idx], 1));
            rin[idx]  = rsqrtf((float)max(dv[i], 1));
        }
        run += dv[i];
    }
    if (b == 0 && t == 0) rowptr[n] = e;
}

__global__ void csr_fill_kernel(const int* __restrict__ src, const int* __restrict__ dst,
                                int* __restrict__ cursor, int* __restrict__ csr, int e) {
    int i = blockIdx.x * blockDim.x + threadIdx.x;
    if (i < e) {
        int p = atomicAdd(cursor + dst[i], 1);
        csr[p] = src[i];
    }
}

// ---------------- FP16 tensor-core GEMM v7: cp.async 3-stage pipe ------------
// C[n,128] = A[n,128] @ W^T ; optional per-row output scale rs (conv1 rout).
// 64x128 tile / 256 threads; W resident (stride 136 halves), A 3-deep cp.async
// ring (stride 24 halves). 44,032 B static smem. Persistent grid-stride tiles.
#define SWH 136
#define SAH2 24
#define GEMM_BLOCKS 444

__device__ __forceinline__ uint32_t smem_u32(const void* p) {
    return (uint32_t)__cvta_generic_to_shared(p);
}
__device__ __forceinline__ void cpa8(uint32_t dst, const __half* src) {
    asm volatile("cp.async.ca.shared.global [%0], [%1], 8;"
                 :: "r"(dst), "l"(src) : "memory");
}
__device__ __forceinline__ void cpa_commit() {
    asm volatile("cp.async.commit_group;" ::: "memory");
}
__device__ __forceinline__ void cpa_wait1() {
    asm volatile("cp.async.wait_group 1;" ::: "memory");
}

__global__ __launch_bounds__(256) void gemm_f16_kernel(
    const __half* __restrict__ A, const __half* __restrict__ Wt,
    const float* __restrict__ rs, __half* __restrict__ C, int n)
{
    __shared__ __half sW[128 * SWH];      // 34816 B
    __shared__ __half sA[3][64 * SAH2];   // 9216 B

    int tid = threadIdx.x;
    int lane = tid & 31;
    int wrp = tid >> 5;
    int wm = wrp & 1;
    int wn = wrp >> 1;
    int tig = lane & 3;
    int gid = lane >> 2;

    // ---- load full W once (2048 uint4, 8/thread)
#pragma unroll
    for (int q = 0; q < 8; q++) {
        int idx = q * 256 + tid;
        int wr = idx >> 4;
        int kb = idx & 15;
        *(uint4*)&sW[wr * SWH + kb * 8] = *(const uint4*)(Wt + wr * DD + kb * 8);
    }

    // ---- ldmatrix base addresses (proven R12 mapping)
    int quad = lane >> 3, wi = lane & 7;
    uint32_t aAddr[3][2];
#pragma unroll
    for (int buf = 0; buf < 3; buf++)
#pragma unroll
        for (int mt = 0; mt < 2; mt++) {
            int ar = wm * 32 + mt * 16 + wi + (quad & 1) * 8;
            aAddr[buf][mt] = smem_u32(&sA[buf][ar * SAH2 + (quad >> 1) * 8]);
        }
    int wi2 = lane & 7, sel = (lane >> 3) & 1;
    uint32_t bAddr[4];
#pragma unroll
    for (int nt = 0; nt < 4; nt++) {
        int br = wn * 32 + nt * 8 + wi2;
        bAddr[nt] = smem_u32(&sW[br * SWH + sel * 8]);
    }

    // A staging: thread -> (arow = tid>>2, ak = (tid&3)*4 halves); 8B cp.async
    int arow = tid >> 2;
    int ak = (tid & 3) << 2;
    uint32_t dstA[3];
#pragma unroll
    for (int buf = 0; buf < 3; buf++)
        dstA[buf] = smem_u32(&sA[buf][arow * SAH2 + ak]);

    int nTiles = (n + 63) >> 6;

    for (int tile = blockIdx.x; tile < nTiles; tile += GEMM_BLOCKS) {
        int row0 = tile * 64;
        int grow = row0 + arow;
        int growc = grow < n ? grow : (n - 1);  // clamp: OOB rows compute garbage
        const __half* Ap = A + (size_t)growc * DD + ak;  // but are never stored

        __syncthreads();  // previous tile's readers done before refilling ring
        cpa8(dstA[0], Ap);        cpa_commit();   // stage 0
        cpa8(dstA[1], Ap + 16);   cpa_commit();   // stage 1

        float acc[2][4][4];
#pragma unroll
        for (int i = 0; i < 2; i++)
#pragma unroll
            for (int j = 0; j < 4; j++)
#pragma unroll
                for (int k = 0; k < 4; k++) acc[i][j][k] = 0.0f;

#pragma unroll
        for (int s = 0; s < 8; s++) {
            cpa_wait1();        // group s complete (<=1 outstanding)
            __syncthreads();    // stage-s data visible; buf[(s+2)%3] free
            if (s < 6) {
                cpa8(dstA[(s + 2) % 3], Ap + (s + 2) * 16);
                cpa_commit();
            }

            uint32_t af[2][4];
#pragma unroll
            for (int mt = 0; mt < 2; mt++) {
                asm volatile(
                    "ldmatrix.sync.aligned.m8n8.x4.shared.b16 {%0,%1,%2,%3}, [%4];"
                    : "=r"(af[mt][0]), "=r"(af[mt][1]), "=r"(af[mt][2]), "=r"(af[mt][3])
                    : "r"(aAddr[s % 3][mt]));
            }
            uint32_t bf[4][2];
            uint32_t boff = (uint32_t)s * 32;
#pragma unroll
            for (int nt = 0; nt < 4; nt++) {
                asm volatile(
                    "ldmatrix.sync.aligned.m8n8.x2.shared.b16 {%0,%1}, [%2];"
                    : "=r"(bf[nt][0]), "=r"(bf[nt][1])
                    : "r"(bAddr[nt] + boff));
            }
#pragma unroll
            for (int nt = 0; nt < 4; nt++) {
#pragma unroll
                for (int mt = 0; mt < 2; mt++) {
                    asm volatile(
                        "mma.sync.aligned.m16n8k16.row.col.f32.f16.f16.f32 "
                        "{%0,%1,%2,%3}, {%4,%5,%6,%7}, {%8,%9}, {%0,%1,%2,%3};"
                        : "+f"(acc[mt][nt][0]), "+f"(acc[mt][nt][1]),
                          "+f"(acc[mt][nt][2]), "+f"(acc[mt][nt][3])
                        : "r"(af[mt][0]), "r"(af[mt][1]), "r"(af[mt][2]), "r"(af[mt][3]),
                          "r"(bf[nt][0]), "r"(bf[nt][1]));
                }
            }
        }

        // ---- writeout, optional per-row output scale (conv1: rout)
#pragma unroll
        for (int mt = 0; mt < 2; mt++) {
            int r0 = row0 + wm * 32 + mt * 16 + gid;
            int r1 = r0 + 8;
            float s0 = 1.0f, s1 = 1.0f;
            if (rs != nullptr) {
                if (r0 < n) s0 = __ldg(rs + r0);
                if (r1 < n) s1 = __ldg(rs + r1);
            }
#pragma unroll
            for (int nt = 0; nt < 4; nt++) {
                int col = wn * 32 + nt * 8 + tig * 2;
                if (r0 < n)
                    *(__half2*)(C + (size_t)r0 * DD + col) =
                        __floats2half2_rn(acc[mt][nt][0] * s0, acc[mt][nt][1] * s0);
                if (r1 < n)
                    *(__half2*)(C + (size_t)r1 * DD + col) =
                        __floats2half2_rn(acc[mt][nt][2] * s1, acc[mt][nt][3] * s1);
            }
        }
    }
}

// ---------------- fused CSR aggregate: half-warp per row, uint4 loads --------
__device__ __forceinline__ void acc_u4(uint4 u, float* a) {
    float2 p0 = __half22float2(*(const __half2*)&u.x);
    float2 p1 = __half22float2(*(const __half2*)&u.y);
    float2 p2 = __half22float2(*(const __half2*)&u.z);
    float2 p3 = __half22float2(*(const __half2*)&u.w);
    a[0] += p0.x; a[1] += p0.y; a[2] += p1.x; a[3] += p1.y;
    a[4] += p2.x; a[5] += p2.y; a[6] += p3.x; a[7] += p3.y;
}

template <bool DO_LN, typename OT>
__global__ void agg_kernel(const int* __restrict__ rowptr, const int* __restrict__ csr,
                           const __half* __restrict__ xw, const float* __restrict__ rin,
                           const float* __restrict__ bias, const __half* __restrict__ feat16,
                           const float* __restrict__ lng, const float* __restrict__ lnb,
                           const float* __restrict__ rout, OT* __restrict__ o, int n)
{
    int row = blockIdx.x * 16 + (threadIdx.x >> 4);
    if (row >= n) return;
    int l16 = threadIdx.x & 15;

    int beg = __ldg(rowptr + row);
    int end = __ldg(rowptr + row + 1);

    const uint4* xwv = (const uint4*)xw + l16;
    float a[8] = {0.f, 0.f, 0.f, 0.f, 0.f, 0.f, 0.f, 0.f};

    int e = beg;
    for (; e + 8 <= end; e += 8) {
        int s[8];
#pragma unroll
        for (int q = 0; q < 8; q++) s[q] = __ldg(csr + e + q);
        uint4 u[8];
#pragma unroll
        for (int q = 0; q < 8; q++) u[q] = __ldg(xwv + (size_t)s[q] * 16);
#pragma unroll
        for (int q = 0; q < 8; q++) acc_u4(u[q], a);
    }
    if (e + 4 <= end) {
        int s[4];
#pragma unroll
        for (int q = 0; q < 4; q++) s[q] = __ldg(csr + e + q);
        uint4 u[4];
#pragma unroll
        for (int q = 0; q < 4; q++) u[q] = __ldg(xwv + (size_t)s[q] * 16);
#pragma unroll
        for (int q = 0; q < 4; q++) acc_u4(u[q], a);
        e += 4;
    }
    if (e + 2 <= end) {
        int s0 = __ldg(csr + e), s1 = __ldg(csr + e + 1);
        uint4 u0 = __ldg(xwv + (size_t)s0 * 16);
        uint4 u1 = __ldg(xwv + (size_t)s1 * 16);
        acc_u4(u0, a);
        acc_u4(u1, a);
        e += 2;
    }
    if (e < end) {
        int s0 = __ldg(csr + e);
        acc_u4(__ldg(xwv + (size_t)s0 * 16), a);
    }

    uint4 uf = __ldg((const uint4*)feat16 + (size_t)row * 16 + l16);
    float f[8];
    {
        float2 p0 = __half22float2(*(const __half2*)&uf.x);
        float2 p1 = __half22float2(*(const __half2*)&uf.y);
        float2 p2 = __half22float2(*(const __half2*)&uf.z);
        float2 p3 = __half22float2(*(const __half2*)&uf.w);
        f[0] = p0.x; f[1] = p0.y; f[2] = p1.x; f[3] = p1.y;
        f[4] = p2.x; f[5] = p2.y; f[6] = p3.x; f[7] = p3.y;
    }

    float s = __ldg(rin + row);
    float4 b0 = ((const float4*)bias)[l16 * 2];
    float4 b1 = ((const float4*)bias)[l16 * 2 + 1];
    float bb[8] = {b0.x, b0.y, b0.z, b0.w, b1.x, b1.y, b1.z, b1.w};
    float h[8];
#pragma unroll
    for (int q = 0; q < 8; q++) h[q] = fmaf(a[q], s, bb[q]) + RESC * f[q];

    if (!DO_LN) {
        float* op = (float*)o + (size_t)row * DD + l16 * 8;
        *(float4*)op = make_float4(h[0], h[1], h[2], h[3]);
        *(float4*)(op + 4) = make_float4(h[4], h[5], h[6], h[7]);
        return;
    }

    float sum = 0.f;
#pragma unroll
    for (int q = 0; q < 8; q++) sum += h[q];
#pragma unroll
    for (int off = 8; off > 0; off >>= 1) sum += __shfl_xor_sync(0xFFFFFFFFu, sum, off);
    float mu = sum * (1.0f / 128.0f);

    float d[8], sq = 0.f;
#pragma unroll
    for (int q = 0; q < 8; q++) { d[q] = h[q] - mu; sq += d[q] * d[q]; }
#pragma unroll
    for (int off = 8; off > 0; off >>= 1) sq += __shfl_xor_sync(0xFFFFFFFFu, sq, off);
    float inv = rsqrtf(sq * (1.0f / 128.0f) + LNEPS);

    float ro = __ldg(rout + row);
    float4 g0 = ((const float4*)lng)[l16 * 2];
    float4 g1 = ((const float4*)lng)[l16 * 2 + 1];
    float4 lb0 = ((const float4*)lnb)[l16 * 2];
    float4 lb1 = ((const float4*)lnb)[l16 * 2 + 1];
    float gg[8] = {g0.x, g0.y, g0.z, g0.w, g1.x, g1.y, g1.z, g1.w};
    float lb[8] = {lb0.x, lb0.y, lb0.z, lb0.w, lb1.x, lb1.y, lb1.z, lb1.w};

    float r[8];
#pragma unroll
    for (int q = 0; q < 8; q++)
        r[q] = fmaxf(fmaf(d[q] * inv, gg[q], lb[q]), 0.0f) * ro;

    uint4 w;
    *(__half2*)&w.x = __floats2half2_rn(r[0], r[1]);
    *(__half2*)&w.y = __floats2half2_rn(r[2], r[3]);
    *(__half2*)&w.z = __floats2half2_rn(r[4], r[5]);
    *(__half2*)&w.w = __floats2half2_rn(r[6], r[7]);
    ((uint4*)((__half*)o + (size_t)row * DD))[l16] = w;
}

// ---------------- launch ------------------------------------------------------
extern "C" void kernel_launch(void* const* d_in, const int* in_sizes, int n_in,
                              void* d_out, int out_size)
{
    const int*   src     = (const int*)d_in[0];
    const int*   dst     = (const int*)d_in[1];
    const float* in_feat = (const float*)d_in[2];
    const float* W1      = (const float*)d_in[3];
    const float* b1      = (const float*)d_in[4];
    const float* W2      = (const float*)d_in[5];
    const float* b2      = (const float*)d_in[6];
    const float* ln1g    = (const float*)d_in[7];
    const float* ln1b    = (const float*)d_in[8];
    const float* ln2g    = (const float*)d_in[9];
    const float* ln2b    = (const float*)d_in[10];
    float* out = (float*)d_out;

    int E = in_sizes[0];
    int n = in_sizes[2] / DD;

    __half *t, *xw, *f16, *w1t, *w2t;
    float *rout, *rin;
    unsigned long long* blob;
    int *rowptr, *cursor, *csrsrc;
    cudaGetSymbolAddress((void**)&t,      g_t);
    cudaGetSymbolAddress((void**)&xw,     g_xw);
    cudaGetSymbolAddress((void**)&f16,    g_f16);
    cudaGetSymbolAddress((void**)&w1t,    g_w1t);
    cudaGetSymbolAddress((void**)&w2t,    g_w2t);
    cudaGetSymbolAddress((void**)&rout,   g_rout);
    cudaGetSymbolAddress((void**)&rin,    g_rin);
    cudaGetSymbolAddress((void**)&blob,   g_blob);
    cudaGetSymbolAddress((void**)&rowptr, g_rowptr);
    cudaGetSymbolAddress((void**)&cursor, g_cursor);
    cudaGetSymbolAddress((void**)&csrsrc, g_csrsrc);
    int* degout = (int*)blob;
    int* degin  = degout + NMAX;
    unsigned long long* state = blob + NMAX;

    const int TB = 256;
    int gridE    = (E + TB - 1) / TB;
    int gridF    = (n * 16 + TB - 1) / TB;
    int gridRow  = (n + 15) / 16;
    int nTiles   = (n + 63) / 64;
    int gridGemm = nTiles < GEMM_BLOCKS ? nTiles : GEMM_BLOCKS;
    int gridScan = (n + 1023) / 1024;

    cudaMemsetAsync(blob, 0, (NMAX + 128) * sizeof(unsigned long long));
    prep_kernel<<<gridE + 128 + gridF, TB>>>(src, dst, degout, degin, W1, W2,
                                             w1t, w2t, in_feat, f16, E, n, gridE);
    scan_lookback_kernel<<<gridScan, 256>>>(degin, degout, state, rowptr, cursor,
                                            rout, rin, n, E);
    csr_fill_kernel<<<gridE, TB>>>(src, dst, cursor, csrsrc, E);

    // conv1: xw = diag(rout) * (feat16 @ W1)   (scale applied at writeout)
    gemm_f16_kernel<<<gridGemm, TB>>>(f16, w1t, rout, xw, n);
    agg_kernel<true, __half><<<gridRow, TB>>>(rowptr, csrsrc, xw, rin, b1, f16,
                                              ln1g, ln1b, rout, t, n);

    // conv2 (t already rout-scaled by LN epilogue)
    gemm_f16_kernel<<<gridGemm, TB>>>(t, w2t, nullptr, xw, n);
    agg_kernel<true, __half><<<gridRow, TB>>>(rowptr, csrsrc, xw, rin, b2, f16,
                                              ln2g, ln2b, rout, t, n);

    // conv3
    gemm_f16_kernel<<<gridGemm, TB>>>(t, w2t, nullptr, xw, n);
    agg_kernel<false, float><<<gridRow, TB>>>(rowptr, csrsrc, xw, rin, b2, f16,
                                              nullptr, nullptr, nullptr, out, n);
}